// round 5
// baseline (speedup 1.0000x reference)
#include <cuda_runtime.h>

#define V_  50257
#define H_  768
#define B_  16
#define T_  128
#define G_  3072          // 4*H
#define KX  1536          // 2*H
#define MROWS 2048        // B*T

// ---------------- scratch (no cudaMalloc allowed) ----------------
__device__ float g_xg[(long)MROWS * G_];   // 25 MB: input-side gate projections
__device__ float g_gates[B_ * G_];         // per-step h @ W_hh^T
__device__ float g_c[B_ * H_];             // running cell state
__device__ float g_lse[MROWS];             // per-row logsumexp
__device__ int   g_last[B_];               // last attended index per example

// ---------------- fast exp (FMA-only, avoids MUFU bottleneck) ----------------
__device__ __forceinline__ float fexp(float x) {
    // valid for x <= 0 (we feed x - rowmax); clamp tail
    x = fmaxf(x, -20.0f);
    float t  = x * 1.4426950408889634f;        // x * log2(e)
    float z  = t + 12582912.0f;                // round-to-nearest via magic number
    float nf = z - 12582912.0f;
    float f  = t - nf;                         // f in [-0.5, 0.5]
    int   n  = (int)nf;
    // 2^f, degree-5 Taylor in ln2 (max err ~2e-6 on the interval)
    float p = fmaf(0.00133335581f, f, 0.00961812911f);
    p = fmaf(p, f, 0.0555041087f);
    p = fmaf(p, f, 0.240226507f);
    p = fmaf(p, f, 0.69314718056f);
    p = fmaf(p, f, 1.0f);
    return p * __int_as_float((n + 127) << 23);
}

// ---------------- setup: copy c0, compute last index ----------------
__global__ void setup_k(const float* __restrict__ dctx, const int* __restrict__ mask) {
    int idx = blockIdx.x * 256 + threadIdx.x;
    if (idx < B_ * H_) g_c[idx] = dctx[idx];
    if (idx >= B_ * H_ && idx < B_ * H_ + B_) {
        int b = idx - B_ * H_;
        int s = 0;
        for (int t = 0; t < T_; t++) s += mask[b * T_ + t];
        g_last[b] = s - 1;
    }
}

// ---------------- GEMM 1: xg = [emb(ids) || append] @ W_ih^T + b_ih ----------------
// 128x128 tile, BK=16, 8x8 per-thread register tile, fused embedding gather.
__global__ __launch_bounds__(256) void xg_gemm(
    const int*   __restrict__ ids,
    const float* __restrict__ emb,
    const float* __restrict__ app,
    const float* __restrict__ Wih,
    const float* __restrict__ bih)
{
    __shared__ __align__(16) float As[16 * 132];
    __shared__ __align__(16) float Bs[16 * 132];
    int tid = threadIdx.x;
    int n0 = blockIdx.x * 128;
    int m0 = blockIdx.y * 128;
    int tx = tid & 15, ty = tid >> 4;

    float acc[8][8];
#pragma unroll
    for (int i = 0; i < 8; i++)
#pragma unroll
        for (int j = 0; j < 8; j++) acc[i][j] = 0.0f;

    for (int k0 = 0; k0 < KX; k0 += 16) {
        // A tile (gathered): rows m0..m0+127, k0..k0+15
#pragma unroll
        for (int i = 0; i < 2; i++) {
            int f4 = tid + i * 256;
            int row = f4 >> 2, kq = f4 & 3;
            int k = k0 + kq * 4;
            int m = m0 + row;
            const float* p;
            if (k < H_) p = emb + (long)ids[m] * H_ + k;
            else        p = app + (long)(m >> 7) * H_ + (k - H_);
            float4 v = *(const float4*)p;
            As[(kq * 4 + 0) * 132 + row] = v.x;
            As[(kq * 4 + 1) * 132 + row] = v.y;
            As[(kq * 4 + 2) * 132 + row] = v.z;
            As[(kq * 4 + 3) * 132 + row] = v.w;
        }
        // B tile: W_ih rows n0..n0+127
#pragma unroll
        for (int i = 0; i < 2; i++) {
            int f4 = tid + i * 256;
            int row = f4 >> 2, kq = f4 & 3;
            int k = k0 + kq * 4;
            float4 v = *(const float4*)(Wih + (long)(n0 + row) * KX + k);
            Bs[(kq * 4 + 0) * 132 + row] = v.x;
            Bs[(kq * 4 + 1) * 132 + row] = v.y;
            Bs[(kq * 4 + 2) * 132 + row] = v.z;
            Bs[(kq * 4 + 3) * 132 + row] = v.w;
        }
        __syncthreads();
#pragma unroll
        for (int kk = 0; kk < 16; kk++) {
            float4 a0 = *(const float4*)&As[kk * 132 + ty * 8];
            float4 a1 = *(const float4*)&As[kk * 132 + ty * 8 + 4];
            float4 b0 = *(const float4*)&Bs[kk * 132 + tx * 8];
            float4 b1 = *(const float4*)&Bs[kk * 132 + tx * 8 + 4];
            float a[8] = {a0.x, a0.y, a0.z, a0.w, a1.x, a1.y, a1.z, a1.w};
            float b[8] = {b0.x, b0.y, b0.z, b0.w, b1.x, b1.y, b1.z, b1.w};
#pragma unroll
            for (int i = 0; i < 8; i++)
#pragma unroll
                for (int j = 0; j < 8; j++)
                    acc[i][j] = fmaf(a[i], b[j], acc[i][j]);
        }
        __syncthreads();
    }
#pragma unroll
    for (int i = 0; i < 8; i++) {
        int m = m0 + ty * 8 + i;
        float* cp = g_xg + (long)m * G_ + n0 + tx * 8;
#pragma unroll
        for (int j4 = 0; j4 < 8; j4 += 4) {
            float4 bv = *(const float4*)(bih + n0 + tx * 8 + j4);
            float4 st;
            st.x = acc[i][j4 + 0] + bv.x;
            st.y = acc[i][j4 + 1] + bv.y;
            st.z = acc[i][j4 + 2] + bv.z;
            st.w = acc[i][j4 + 3] + bv.w;
            *(float4*)(cp + j4) = st;
        }
    }
}

// ---------------- per-step: gates_mm = h @ W_hh^T  (M=16, N=3072, K=768) ----------------
// Each warp owns 2 output rows; lanes parallelize K (coalesced W loads, broadcast-free),
// then butterfly-reduce. W_hh read exactly once per step (L2 resident).
__global__ __launch_bounds__(256) void gates_mm(
    const float* __restrict__ hsrc, int hstride,
    const float* __restrict__ Whh)
{
    __shared__ __align__(16) float hs[B_ * H_];   // 48 KB
    int tid = threadIdx.x;
    for (int i = tid; i < B_ * H_; i += 256) {
        int b = i / H_, u = i - b * H_;
        hs[i] = hsrc[(long)b * hstride + u];
    }
    __syncthreads();

    int wid = tid >> 5, lane = tid & 31;
    int r0 = blockIdx.x * 16 + wid * 2;
    int r1 = r0 + 1;
    const float4* w0p = (const float4*)(Whh + (long)r0 * H_);
    const float4* w1p = (const float4*)(Whh + (long)r1 * H_);
    const float4* h4  = (const float4*)hs;

    float acc0[16], acc1[16];
#pragma unroll
    for (int b = 0; b < 16; b++) { acc0[b] = 0.0f; acc1[b] = 0.0f; }

#pragma unroll
    for (int ch = 0; ch < 6; ch++) {
        int k4 = ch * 32 + lane;
        float4 w0 = w0p[k4];
        float4 w1 = w1p[k4];
#pragma unroll
        for (int b = 0; b < 16; b++) {
            float4 h = h4[b * 192 + k4];
            acc0[b] = fmaf(w0.x, h.x, fmaf(w0.y, h.y, fmaf(w0.z, h.z, fmaf(w0.w, h.w, acc0[b]))));
            acc1[b] = fmaf(w1.x, h.x, fmaf(w1.y, h.y, fmaf(w1.z, h.z, fmaf(w1.w, h.w, acc1[b]))));
        }
    }
#pragma unroll
    for (int b = 0; b < 16; b++) {
        float v0 = acc0[b], v1 = acc1[b];
#pragma unroll
        for (int off = 16; off; off >>= 1) {
            v0 += __shfl_xor_sync(0xffffffffu, v0, off);
            v1 += __shfl_xor_sync(0xffffffffu, v1, off);
        }
        if (lane == b) {
            g_gates[b * G_ + r0] = v0;
            g_gates[b * G_ + r1] = v1;
        }
    }
}

// ---------------- per-step pointwise LSTM cell ----------------
__global__ void lstm_pw(int t, float* __restrict__ allh, float* __restrict__ selctx,
                        const float* __restrict__ bhh)
{
    int idx = blockIdx.x * 256 + threadIdx.x;
    if (idx >= B_ * H_) return;
    int b = idx / H_, u = idx - b * H_;
    long m = (long)b * T_ + t;
    const float* xr = g_xg + m * G_;
    const float* gr = g_gates + (long)b * G_;
    float xi = gr[u]          + xr[u]          + bhh[u];
    float xf = gr[H_ + u]     + xr[H_ + u]     + bhh[H_ + u];
    float xg = gr[2 * H_ + u] + xr[2 * H_ + u] + bhh[2 * H_ + u];
    float xo = gr[3 * H_ + u] + xr[3 * H_ + u] + bhh[3 * H_ + u];
    float si = 1.0f / (1.0f + expf(-xi));
    float sf = 1.0f / (1.0f + expf(-xf));
    float so = 1.0f / (1.0f + expf(-xo));
    float tg = tanhf(xg);
    float c = sf * g_c[idx] + si * tg;
    float h = so * tanhf(c);
    g_c[idx] = c;
    allh[m * H_ + u] = h;
    if (t == g_last[b]) selctx[idx] = c;
}

// ---------------- GEMM 3: logits = all_hiddens @ lm_w^T + lm_b (into lprobs region) ----------------
__global__ __launch_bounds__(256) void logits_gemm(
    const float* __restrict__ Ah,
    const float* __restrict__ lmw,
    const float* __restrict__ lmb,
    float* __restrict__ lp)
{
    __shared__ __align__(16) float As[16 * 132];
    __shared__ __align__(16) float Bs[16 * 132];
    int tid = threadIdx.x;
    int n0 = blockIdx.x * 128;
    int m0 = blockIdx.y * 128;
    int tx = tid & 15, ty = tid >> 4;

    float acc[8][8];
#pragma unroll
    for (int i = 0; i < 8; i++)
#pragma unroll
        for (int j = 0; j < 8; j++) acc[i][j] = 0.0f;

    for (int k0 = 0; k0 < H_; k0 += 16) {
#pragma unroll
        for (int i = 0; i < 2; i++) {
            int f4 = tid + i * 256;
            int row = f4 >> 2, kq = f4 & 3;
            int k = k0 + kq * 4;
            float4 v = *(const float4*)(Ah + (long)(m0 + row) * H_ + k);
            As[(kq * 4 + 0) * 132 + row] = v.x;
            As[(kq * 4 + 1) * 132 + row] = v.y;
            As[(kq * 4 + 2) * 132 + row] = v.z;
            As[(kq * 4 + 3) * 132 + row] = v.w;
        }
#pragma unroll
        for (int i = 0; i < 2; i++) {
            int f4 = tid + i * 256;
            int row = f4 >> 2, kq = f4 & 3;
            int k = k0 + kq * 4;
            int n = n0 + row;
            float4 v = make_float4(0.f, 0.f, 0.f, 0.f);
            if (n < V_) v = *(const float4*)(lmw + (long)n * H_ + k);
            Bs[(kq * 4 + 0) * 132 + row] = v.x;
            Bs[(kq * 4 + 1) * 132 + row] = v.y;
            Bs[(kq * 4 + 2) * 132 + row] = v.z;
            Bs[(kq * 4 + 3) * 132 + row] = v.w;
        }
        __syncthreads();
#pragma unroll
        for (int kk = 0; kk < 16; kk++) {
            float4 a0 = *(const float4*)&As[kk * 132 + ty * 8];
            float4 a1 = *(const float4*)&As[kk * 132 + ty * 8 + 4];
            float4 b0 = *(const float4*)&Bs[kk * 132 + tx * 8];
            float4 b1 = *(const float4*)&Bs[kk * 132 + tx * 8 + 4];
            float a[8] = {a0.x, a0.y, a0.z, a0.w, a1.x, a1.y, a1.z, a1.w};
            float b[8] = {b0.x, b0.y, b0.z, b0.w, b1.x, b1.y, b1.z, b1.w};
#pragma unroll
            for (int i = 0; i < 8; i++)
#pragma unroll
                for (int j = 0; j < 8; j++)
                    acc[i][j] = fmaf(a[i], b[j], acc[i][j]);
        }
        __syncthreads();
    }
    // scalar stores (row stride 50257 is odd -> no float4 alignment)
#pragma unroll
    for (int i = 0; i < 8; i++) {
        long m = m0 + ty * 8 + i;
        float* cp = lp + m * V_;
#pragma unroll
        for (int j = 0; j < 8; j++) {
            int n = n0 + tx * 8 + j;
            if (n < V_) cp[n] = acc[i][j] + lmb[n];
        }
    }
}

// ---------------- log-softmax: per-row max + sum(exp), then in-place subtract ----------------
__global__ void lse_k(const float* __restrict__ lp) {
    __shared__ float red[256];
    int m = blockIdx.x;
    int tid = threadIdx.x;
    const float* row = lp + (long)m * V_;
    float mx = -1e30f;
    for (int j = tid; j < V_; j += 256) mx = fmaxf(mx, row[j]);
    red[tid] = mx; __syncthreads();
    for (int s = 128; s; s >>= 1) { if (tid < s) red[tid] = fmaxf(red[tid], red[tid + s]); __syncthreads(); }
    mx = red[0];
    __syncthreads();
    float sum = 0.0f;
    for (int j = tid; j < V_; j += 256) sum += fexp(row[j] - mx);
    red[tid] = sum; __syncthreads();
    for (int s = 128; s; s >>= 1) { if (tid < s) red[tid] += red[tid + s]; __syncthreads(); }
    if (tid == 0) g_lse[m] = mx + logf(red[0]);
}

__global__ void sub_k(float* __restrict__ lp) {
    int m = blockIdx.y;
    int j = blockIdx.x * 256 + threadIdx.x;
    if (j < V_) lp[(long)m * V_ + j] -= g_lse[m];
}

// ---------------- launch ----------------
extern "C" void kernel_launch(void* const* d_in, const int* in_sizes, int n_in,
                              void* d_out, int out_size)
{
    const int*   ids  = (const int*)d_in[0];
    const int*   mask = (const int*)d_in[1];
    const float* dh   = (const float*)d_in[2];
    const float* dc   = (const float*)d_in[3];
    const float* dapp = (const float*)d_in[4];
    const float* emb  = (const float*)d_in[5];
    const float* Wih  = (const float*)d_in[6];
    const float* Whh  = (const float*)d_in[7];
    const float* bih  = (const float*)d_in[8];
    const float* bhh  = (const float*)d_in[9];
    const float* lmw  = (const float*)d_in[10];
    const float* lmb  = (const float*)d_in[11];
    (void)in_sizes; (void)n_in; (void)out_size;

    float* out    = (float*)d_out;
    float* allh   = out;                              // [B,T,H]
    float* selctx = out + (long)MROWS * H_;           // [B,H]
    float* lp     = selctx + B_ * H_;                 // [B,T,V]

    setup_k<<<49, 256>>>(dc, mask);
    xg_gemm<<<dim3(G_ / 128, MROWS / 128), 256>>>(ids, emb, dapp, Wih, bih);

    for (int t = 0; t < T_; t++) {
        const float* hsrc = (t == 0) ? dh : (allh + (long)(t - 1) * H_);
        int hstride = (t == 0) ? H_ : T_ * H_;
        gates_mm<<<192, 256>>>(hsrc, hstride, Whh);
        lstm_pw<<<48, 256>>>(t, allh, selctx, bhh);
    }

    logits_gemm<<<dim3((V_ + 127) / 128, MROWS / 128), 256>>>(allh, lmw, lmb, lp);
    lse_k<<<MROWS, 256>>>(lp);
    sub_k<<<dim3((V_ + 255) / 256, MROWS), 256>>>(lp);
}

// round 8
// speedup vs baseline: 1.5931x; 1.5931x over previous
#include <cuda_runtime.h>
#include <cuda_bf16.h>
#include <cstdint>

#define V_  50257
#define H_  768
#define B_  16
#define T_  128
#define G_  3072          // 4*H
#define KX  1536          // 2*H
#define MROWS 2048        // B*T

// ================= scratch (no cudaMalloc allowed) =================
__device__ float g_xg[(long)MROWS * G_];                 // input-side gate projections
__device__ float g_c[B_ * H_];
__device__ float g_lse[MROWS];
__device__ int   g_last[B_];
__device__ __nv_bfloat16 g_whi[(long)V_ * H_];           // lm_w hi
__device__ __nv_bfloat16 g_wlo[(long)V_ * H_];           // lm_w lo
__device__ __nv_bfloat16 g_ahi[(long)MROWS * H_];        // hiddens hi
__device__ __nv_bfloat16 g_alo[(long)MROWS * H_];        // hiddens lo
__device__ __nv_bfloat16 g_xah[(long)MROWS * KX];        // [emb||app] hi
__device__ __nv_bfloat16 g_xal[(long)MROWS * KX];        // [emb||app] lo
__device__ __nv_bfloat16 g_wihh[(long)G_ * KX];          // W_ih hi
__device__ __nv_bfloat16 g_wihl[(long)G_ * KX];          // W_ih lo

// ================= small ptx helpers (baseline PTX only) =================
__device__ __forceinline__ uint32_t smem_to_u32(const void* p) {
    uint32_t a;
    asm("{ .reg .u64 t; cvta.to.shared.u64 t, %1; cvt.u32.u64 %0, t; }" : "=r"(a) : "l"(p));
    return a;
}
__device__ __forceinline__ void cpasync16(uint32_t dst, const void* src, uint32_t sz) {
    asm volatile("cp.async.cg.shared.global [%0], [%1], 16, %2;\n"
        :: "r"(dst), "l"(src), "r"(sz) : "memory");
}
__device__ __forceinline__ void ldm_x4(uint32_t addr, uint32_t* r) {
    asm volatile("ldmatrix.sync.aligned.m8n8.x4.shared.b16 {%0,%1,%2,%3}, [%4];"
        : "=r"(r[0]), "=r"(r[1]), "=r"(r[2]), "=r"(r[3]) : "r"(addr));
}
__device__ __forceinline__ void mma16816(float* d, const uint32_t* a, const uint32_t* b) {
    asm volatile("mma.sync.aligned.m16n8k16.row.col.f32.bf16.bf16.f32 "
        "{%0,%1,%2,%3}, {%4,%5,%6,%7}, {%8,%9}, {%0,%1,%2,%3};"
        : "+f"(d[0]), "+f"(d[1]), "+f"(d[2]), "+f"(d[3])
        : "r"(a[0]), "r"(a[1]), "r"(a[2]), "r"(a[3]), "r"(b[0]), "r"(b[1]));
}

// ================= fast exp =================
__device__ __forceinline__ float fexp(float x) {
    x = fmaxf(x, -20.0f);
    float t  = x * 1.4426950408889634f;
    float z  = t + 12582912.0f;
    float nf = z - 12582912.0f;
    float f  = t - nf;
    int   n  = (int)nf;
    float p = fmaf(0.00133335581f, f, 0.00961812911f);
    p = fmaf(p, f, 0.0555041087f);
    p = fmaf(p, f, 0.240226507f);
    p = fmaf(p, f, 0.69314718056f);
    p = fmaf(p, f, 1.0f);
    return p * __int_as_float((n + 127) << 23);
}

// ================= setup =================
__global__ void setup_k(const float* __restrict__ dctx, const int* __restrict__ mask) {
    int idx = blockIdx.x * 256 + threadIdx.x;
    if (idx < B_ * H_) g_c[idx] = dctx[idx];
    if (idx >= B_ * H_ && idx < B_ * H_ + B_) {
        int b = idx - B_ * H_;
        int s = 0;
        for (int t = 0; t < T_; t++) s += mask[b * T_ + t];
        g_last[b] = s - 1;
    }
}

// ================= hi/lo bf16 conversion =================
__global__ void conv_k(const float* __restrict__ src, __nv_bfloat16* __restrict__ hi,
                       __nv_bfloat16* __restrict__ lo, long n4) {
    long i = (long)blockIdx.x * 256 + threadIdx.x;
    long stride = (long)gridDim.x * 256;
    for (; i < n4; i += stride) {
        float4 v = ((const float4*)src)[i];
        __nv_bfloat16 h0 = __float2bfloat16(v.x), h1 = __float2bfloat16(v.y);
        __nv_bfloat16 h2 = __float2bfloat16(v.z), h3 = __float2bfloat16(v.w);
        __nv_bfloat16 l0 = __float2bfloat16(v.x - __bfloat162float(h0));
        __nv_bfloat16 l1 = __float2bfloat16(v.y - __bfloat162float(h1));
        __nv_bfloat16 l2 = __float2bfloat16(v.z - __bfloat162float(h2));
        __nv_bfloat16 l3 = __float2bfloat16(v.w - __bfloat162float(h3));
        ((__nv_bfloat162*)hi)[i * 2 + 0] = __nv_bfloat162(h0, h1);
        ((__nv_bfloat162*)hi)[i * 2 + 1] = __nv_bfloat162(h2, h3);
        ((__nv_bfloat162*)lo)[i * 2 + 0] = __nv_bfloat162(l0, l1);
        ((__nv_bfloat162*)lo)[i * 2 + 1] = __nv_bfloat162(l2, l3);
    }
}

// build [emb(ids) || append] as hi/lo bf16, rows = MROWS, K = KX
__global__ void conv_gather(const int* __restrict__ ids, const float* __restrict__ emb,
                            const float* __restrict__ app,
                            __nv_bfloat16* __restrict__ hi, __nv_bfloat16* __restrict__ lo) {
    long total = (long)MROWS * (KX / 4);
    long i = (long)blockIdx.x * 256 + threadIdx.x;
    long stride = (long)gridDim.x * 256;
    for (; i < total; i += stride) {
        int m = (int)(i / (KX / 4));
        int q = (int)(i - (long)m * (KX / 4));
        int k = q * 4;
        const float* p;
        if (k < H_) p = emb + (long)ids[m] * H_ + k;
        else        p = app + (long)(m >> 7) * H_ + (k - H_);
        float4 v = *(const float4*)p;
        __nv_bfloat16 h0 = __float2bfloat16(v.x), h1 = __float2bfloat16(v.y);
        __nv_bfloat16 h2 = __float2bfloat16(v.z), h3 = __float2bfloat16(v.w);
        __nv_bfloat16 l0 = __float2bfloat16(v.x - __bfloat162float(h0));
        __nv_bfloat16 l1 = __float2bfloat16(v.y - __bfloat162float(h1));
        __nv_bfloat16 l2 = __float2bfloat16(v.z - __bfloat162float(h2));
        __nv_bfloat16 l3 = __float2bfloat16(v.w - __bfloat162float(h3));
        long o = (long)m * (KX / 2) + q * 2;
        ((__nv_bfloat162*)hi)[o + 0] = __nv_bfloat162(h0, h1);
        ((__nv_bfloat162*)hi)[o + 1] = __nv_bfloat162(h2, h3);
        ((__nv_bfloat162*)lo)[o + 0] = __nv_bfloat162(l0, l1);
        ((__nv_bfloat162*)lo)[o + 1] = __nv_bfloat162(l2, l3);
    }
}

// ================= HMMA GEMM (hi/lo 3-term): C[M,N] = A[M,K] @ B[N,K]^T + bias =================
// Block 128x128, BK=32, 8 warps (2x4), warp tile 64x32, mma.m16n8k16 bf16.
#define LDSW 80                  // padded row stride in bytes (40 halves)
#define ATILE (128 * LDSW)       // 10240 B per matrix tile
#define HSTAGE (4 * ATILE)       // Ahi, Alo, Bhi, Blo
#define HSMEM (2 * HSTAGE)       // 81920 B, double buffered

__global__ __launch_bounds__(256, 1) void hmma_gemm(
    const __nv_bfloat16* __restrict__ Ah, const __nv_bfloat16* __restrict__ Al,
    const __nv_bfloat16* __restrict__ Bh, const __nv_bfloat16* __restrict__ Bl,
    const float* __restrict__ bias, float* __restrict__ C,
    int K, int Nvalid)
{
    extern __shared__ __align__(128) char smem[];
    uint32_t sb = smem_to_u32(smem);
    int tid = threadIdx.x;
    int lane = tid & 31, wid = tid >> 5;
    int wm = wid & 1, wn = wid >> 1;
    int n0 = blockIdx.x * 128;
    int m0 = blockIdx.y * 128;
    int NK = K >> 5;

    float acc[4][4][4];
#pragma unroll
    for (int a = 0; a < 4; a++)
#pragma unroll
        for (int b = 0; b < 4; b++)
#pragma unroll
            for (int c = 0; c < 4; c++) acc[a][b][c] = 0.0f;

    // ---- stage loader ----
    auto load_stage = [&](int stg) {
        int k0 = stg << 5;
        uint32_t db = sb + (stg & 1) * HSTAGE;
        int row = tid >> 2;          // 0..63
        int q   = tid & 3;
#pragma unroll
        for (int i = 0; i < 8; i++) {
            int mat = i >> 1;
            int r = (i & 1) * 64 + row;
            uint32_t dst = db + mat * ATILE + r * LDSW + q * 16;
            const __nv_bfloat16* src;
            uint32_t sz = 16;
            if (mat == 0)      src = Ah + (long)(m0 + r) * K + k0 + q * 8;
            else if (mat == 1) src = Al + (long)(m0 + r) * K + k0 + q * 8;
            else {
                int n = n0 + r;
                const __nv_bfloat16* base = (mat == 2) ? Bh : Bl;
                if (n >= Nvalid) { n = 0; sz = 0; }
                src = base + (long)n * K + k0 + q * 8;
            }
            cpasync16(dst, src, sz);
        }
    };

    load_stage(0);
    asm volatile("cp.async.commit_group;" ::: "memory");

    // frag address precompute
    int a_row = lane & 15;                   // within 16-row frag
    int a_kh  = (lane >> 4) << 3;            // 0 or 8 halves
    int b_g   = lane >> 3;
    int b_nr  = ((b_g >> 1) << 3) + (lane & 7);  // 0..15 within 16-n group
    int b_kh  = (b_g & 1) << 3;

    for (int c = 0; c < NK; c++) {
        if (c + 1 < NK) {
            load_stage(c + 1);
            asm volatile("cp.async.commit_group;" ::: "memory");
            asm volatile("cp.async.wait_group 1;" ::: "memory");
        } else {
            asm volatile("cp.async.wait_group 0;" ::: "memory");
        }
        __syncthreads();

        uint32_t aB = sb + (c & 1) * HSTAGE;
#pragma unroll
        for (int kk = 0; kk < 32; kk += 16) {
            uint32_t bh[8], bl[8], af[16];
            // B hi/lo frags (4 n-frags each)
#pragma unroll
            for (int f2 = 0; f2 < 2; f2++) {
                uint32_t off = (uint32_t)((wn * 32 + f2 * 16 + b_nr) * LDSW + (kk + b_kh) * 2);
                ldm_x4(aB + 2 * ATILE + off, &bh[f2 * 4]);
                ldm_x4(aB + 3 * ATILE + off, &bl[f2 * 4]);
            }
            // A hi frags + mma vs Bhi and Blo
#pragma unroll
            for (int fm = 0; fm < 4; fm++) {
                uint32_t off = (uint32_t)((wm * 64 + fm * 16 + a_row) * LDSW + (kk + a_kh) * 2);
                ldm_x4(aB + off, &af[fm * 4]);
            }
#pragma unroll
            for (int fm = 0; fm < 4; fm++)
#pragma unroll
                for (int fn = 0; fn < 4; fn++) {
                    mma16816(acc[fm][fn], &af[fm * 4], &bh[fn * 2]);
                    mma16816(acc[fm][fn], &af[fm * 4], &bl[fn * 2]);
                }
            // A lo frags + mma vs Bhi
#pragma unroll
            for (int fm = 0; fm < 4; fm++) {
                uint32_t off = (uint32_t)((wm * 64 + fm * 16 + a_row) * LDSW + (kk + a_kh) * 2);
                ldm_x4(aB + ATILE + off, &af[fm * 4]);
            }
#pragma unroll
            for (int fm = 0; fm < 4; fm++)
#pragma unroll
                for (int fn = 0; fn < 4; fn++)
                    mma16816(acc[fm][fn], &af[fm * 4], &bh[fn * 2]);
        }
        __syncthreads();
    }

    // ---- epilogue: direct global stores + bias ----
    int mbase = m0 + wm * 64 + (lane >> 2);
    int nbase = n0 + wn * 32 + ((lane & 3) << 1);
#pragma unroll
    for (int fm = 0; fm < 4; fm++) {
#pragma unroll
        for (int fn = 0; fn < 4; fn++) {
            int m = mbase + fm * 16;
            int n = nbase + fn * 8;
            float* d = acc[fm][fn];
            if (n < Nvalid) {
                float bv = bias[n];
                C[(long)m * Nvalid + n]       = d[0] + bv;
                C[(long)(m + 8) * Nvalid + n] = d[2] + bv;
            }
            if (n + 1 < Nvalid) {
                float bv = bias[n + 1];
                C[(long)m * Nvalid + n + 1]       = d[1] + bv;
                C[(long)(m + 8) * Nvalid + n + 1] = d[3] + bv;
            }
        }
    }
}

// ================= fused LSTM step: gates GEMM + pointwise =================
__global__ __launch_bounds__(256) void lstm_step(
    int t, const float* __restrict__ hsrc, int hstride,
    const float* __restrict__ Whh, const float* __restrict__ bhh,
    float* __restrict__ allh, float* __restrict__ selctx)
{
    __shared__ __align__(16) float hs[B_ * H_];
    int tid = threadIdx.x;
    for (int i = tid; i < B_ * H_; i += 256) {
        int b = i / H_, uu = i - b * H_;
        hs[i] = hsrc[(long)b * hstride + uu];
    }
    __syncthreads();

    int wid = tid >> 5, lane = tid & 31;
    int u = blockIdx.x * 8 + wid;
    const float4* wp0 = (const float4*)(Whh + (long)(0 * H_ + u) * H_);
    const float4* wp1 = (const float4*)(Whh + (long)(1 * H_ + u) * H_);
    const float4* wp2 = (const float4*)(Whh + (long)(2 * H_ + u) * H_);
    const float4* wp3 = (const float4*)(Whh + (long)(3 * H_ + u) * H_);
    const float4* h4 = (const float4*)hs;

    float acc[4][16];
#pragma unroll
    for (int g = 0; g < 4; g++)
#pragma unroll
        for (int b = 0; b < 16; b++) acc[g][b] = 0.0f;

#pragma unroll
    for (int ch = 0; ch < 6; ch++) {
        int k4 = ch * 32 + lane;
        float4 w0 = wp0[k4], w1 = wp1[k4], w2 = wp2[k4], w3 = wp3[k4];
#pragma unroll
        for (int b = 0; b < 16; b++) {
            float4 h = h4[b * 192 + k4];
            acc[0][b] = fmaf(w0.x, h.x, fmaf(w0.y, h.y, fmaf(w0.z, h.z, fmaf(w0.w, h.w, acc[0][b]))));
            acc[1][b] = fmaf(w1.x, h.x, fmaf(w1.y, h.y, fmaf(w1.z, h.z, fmaf(w1.w, h.w, acc[1][b]))));
            acc[2][b] = fmaf(w2.x, h.x, fmaf(w2.y, h.y, fmaf(w2.z, h.z, fmaf(w2.w, h.w, acc[2][b]))));
            acc[3][b] = fmaf(w3.x, h.x, fmaf(w3.y, h.y, fmaf(w3.z, h.z, fmaf(w3.w, h.w, acc[3][b]))));
        }
    }
#pragma unroll
    for (int g = 0; g < 4; g++)
#pragma unroll
        for (int b = 0; b < 16; b++) {
            float v = acc[g][b];
#pragma unroll
            for (int off = 16; off; off >>= 1) v += __shfl_xor_sync(0xffffffffu, v, off);
            acc[g][b] = v;
        }

    if (lane < 16) {
        int b = lane;
        long m = (long)b * T_ + t;
        const float* xr = g_xg + m * G_;
        float xi = acc[0][b] + xr[0 * H_ + u] + bhh[0 * H_ + u];
        float xf = acc[1][b] + xr[1 * H_ + u] + bhh[1 * H_ + u];
        float xg = acc[2][b] + xr[2 * H_ + u] + bhh[2 * H_ + u];
        float xo = acc[3][b] + xr[3 * H_ + u] + bhh[3 * H_ + u];
        float si = 1.0f / (1.0f + expf(-xi));
        float sf = 1.0f / (1.0f + expf(-xf));
        float so = 1.0f / (1.0f + expf(-xo));
        float tg = tanhf(xg);
        float c = sf * g_c[b * H_ + u] + si * tg;
        float h = so * tanhf(c);
        g_c[b * H_ + u] = c;
        allh[m * H_ + u] = h;
        if (t == g_last[b]) selctx[b * H_ + u] = c;
    }
}

// ================= log-softmax =================
__global__ void lse_k(const float* __restrict__ lp) {
    __shared__ float red[256];
    int m = blockIdx.x;
    int tid = threadIdx.x;
    const float* row = lp + (long)m * V_;
    float mx = -1e30f;
    for (int j = tid; j < V_; j += 256) mx = fmaxf(mx, row[j]);
    red[tid] = mx; __syncthreads();
    for (int s = 128; s; s >>= 1) { if (tid < s) red[tid] = fmaxf(red[tid], red[tid + s]); __syncthreads(); }
    mx = red[0];
    __syncthreads();
    float sum = 0.0f;
    for (int j = tid; j < V_; j += 256) sum += fexp(row[j] - mx);
    red[tid] = sum; __syncthreads();
    for (int s = 128; s; s >>= 1) { if (tid < s) red[tid] += red[tid + s]; __syncthreads(); }
    if (tid == 0) g_lse[m] = mx + logf(red[0]);
}

__global__ void sub_k(float* __restrict__ lp) {
    int m = blockIdx.y;
    int j = blockIdx.x * 256 + threadIdx.x;
    if (j < V_) lp[(long)m * V_ + j] -= g_lse[m];
}

// ================= launch =================
extern "C" void kernel_launch(void* const* d_in, const int* in_sizes, int n_in,
                              void* d_out, int out_size)
{
    const int*   ids  = (const int*)d_in[0];
    const int*   mask = (const int*)d_in[1];
    const float* dh   = (const float*)d_in[2];
    const float* dc   = (const float*)d_in[3];
    const float* dapp = (const float*)d_in[4];
    const float* emb  = (const float*)d_in[5];
    const float* Wih  = (const float*)d_in[6];
    const float* Whh  = (const float*)d_in[7];
    const float* bih  = (const float*)d_in[8];
    const float* bhh  = (const float*)d_in[9];
    const float* lmw  = (const float*)d_in[10];
    const float* lmb  = (const float*)d_in[11];
    (void)in_sizes; (void)n_in; (void)out_size;

    float* out    = (float*)d_out;
    float* allh   = out;
    float* selctx = out + (long)MROWS * H_;
    float* lp     = selctx + B_ * H_;

    static int attr_set = 0;
    if (!attr_set) {
        cudaFuncSetAttribute(hmma_gemm, cudaFuncAttributeMaxDynamicSharedMemorySize, HSMEM);
        attr_set = 1;
    }

    __nv_bfloat16 *whi, *wlo, *ahi, *alo, *xah, *xal, *wihh, *wihl;
    float* xg;
    cudaGetSymbolAddress((void**)&whi, g_whi);
    cudaGetSymbolAddress((void**)&wlo, g_wlo);
    cudaGetSymbolAddress((void**)&ahi, g_ahi);
    cudaGetSymbolAddress((void**)&alo, g_alo);
    cudaGetSymbolAddress((void**)&xah, g_xah);
    cudaGetSymbolAddress((void**)&xal, g_xal);
    cudaGetSymbolAddress((void**)&wihh, g_wihh);
    cudaGetSymbolAddress((void**)&wihl, g_wihl);
    cudaGetSymbolAddress((void**)&xg, g_xg);

    setup_k<<<49, 256>>>(dc, mask);

    // conversions for xg GEMM
    conv_gather<<<1024, 256>>>(ids, emb, dapp, xah, xal);
    conv_k<<<1024, 256>>>(Wih, wihh, wihl, (long)G_ * KX / 4);

    // xg = [emb||app] @ W_ih^T + b_ih via HMMA hi/lo
    hmma_gemm<<<dim3(G_ / 128, MROWS / 128), 256, HSMEM>>>(
        xah, xal, wihh, wihl, bih, xg, KX, G_);

    // convert lm_w while the recurrence runs after (stream-ordered anyway)
    conv_k<<<4096, 256>>>(lmw, whi, wlo, (long)V_ * H_ / 4);

    for (int t = 0; t < T_; t++) {
        const float* hsrc = (t == 0) ? dh : (allh + (long)(t - 1) * H_);
        int hstride = (t == 0) ? H_ : T_ * H_;
        lstm_step<<<96, 256>>>(t, hsrc, hstride, Whh, bhh, allh, selctx);
    }

    conv_k<<<1536, 256>>>(allh, ahi, alo, (long)MROWS * H_ / 4);

    // logits = all_hiddens @ lm_w^T + lm_b via HMMA hi/lo
    hmma_gemm<<<dim3((V_ + 127) / 128, MROWS / 128), 256, HSMEM>>>(
        ahi, alo, whi, wlo, lmb, lp, H_, V_);

    lse_k<<<MROWS, 256>>>(lp);
    sub_k<<<dim3((V_ + 255) / 256, MROWS), 256>>>(lp);
}

// round 9
// speedup vs baseline: 1.9541x; 1.2266x over previous
#include <cuda_runtime.h>
#include <cuda_bf16.h>
#include <cstdint>

#define V_  50257
#define H_  768
#define B_  16
#define T_  128
#define G_  3072          // 4*H
#define KX  1536          // 2*H
#define MROWS 2048        // B*T

#define LSTM_BLOCKS 128
#define LSTM_WARPS  6     // units per block; 128*6 = 768 = H_

// ================= scratch (no cudaMalloc allowed) =================
__device__ float g_xg[(long)MROWS * G_];                 // input-side gate projections
__device__ float g_lse[MROWS];
__device__ int   g_last[B_];
__device__ unsigned g_bar;                               // grid barrier counter
__device__ __nv_bfloat16 g_whi[(long)V_ * H_];           // lm_w hi
__device__ __nv_bfloat16 g_wlo[(long)V_ * H_];           // lm_w lo
__device__ __nv_bfloat16 g_ahi[(long)MROWS * H_];        // hiddens hi
__device__ __nv_bfloat16 g_alo[(long)MROWS * H_];        // hiddens lo
__device__ __nv_bfloat16 g_xah[(long)MROWS * KX];        // [emb||app] hi
__device__ __nv_bfloat16 g_xal[(long)MROWS * KX];        // [emb||app] lo
__device__ __nv_bfloat16 g_wihh[(long)G_ * KX];          // W_ih hi
__device__ __nv_bfloat16 g_wihl[(long)G_ * KX];          // W_ih lo

// ================= small ptx helpers (baseline PTX only) =================
__device__ __forceinline__ uint32_t smem_to_u32(const void* p) {
    uint32_t a;
    asm("{ .reg .u64 t; cvta.to.shared.u64 t, %1; cvt.u32.u64 %0, t; }" : "=r"(a) : "l"(p));
    return a;
}
__device__ __forceinline__ void cpasync16(uint32_t dst, const void* src, uint32_t sz) {
    asm volatile("cp.async.cg.shared.global [%0], [%1], 16, %2;\n"
        :: "r"(dst), "l"(src), "r"(sz) : "memory");
}
__device__ __forceinline__ void ldm_x4(uint32_t addr, uint32_t* r) {
    asm volatile("ldmatrix.sync.aligned.m8n8.x4.shared.b16 {%0,%1,%2,%3}, [%4];"
        : "=r"(r[0]), "=r"(r[1]), "=r"(r[2]), "=r"(r[3]) : "r"(addr));
}
__device__ __forceinline__ void mma16816(float* d, const uint32_t* a, const uint32_t* b) {
    asm volatile("mma.sync.aligned.m16n8k16.row.col.f32.bf16.bf16.f32 "
        "{%0,%1,%2,%3}, {%4,%5,%6,%7}, {%8,%9}, {%0,%1,%2,%3};"
        : "+f"(d[0]), "+f"(d[1]), "+f"(d[2]), "+f"(d[3])
        : "r"(a[0]), "r"(a[1]), "r"(a[2]), "r"(a[3]), "r"(b[0]), "r"(b[1]));
}
__device__ __forceinline__ unsigned ld_acq(const unsigned* p) {
    unsigned v;
    asm volatile("ld.acquire.gpu.global.u32 %0, [%1];" : "=r"(v) : "l"(p) : "memory");
    return v;
}

// ================= fast exp =================
__device__ __forceinline__ float fexp(float x) {
    x = fmaxf(x, -20.0f);
    float t  = x * 1.4426950408889634f;
    float z  = t + 12582912.0f;
    float nf = z - 12582912.0f;
    float f  = t - nf;
    int   n  = (int)nf;
    float p = fmaf(0.00133335581f, f, 0.00961812911f);
    p = fmaf(p, f, 0.0555041087f);
    p = fmaf(p, f, 0.240226507f);
    p = fmaf(p, f, 0.69314718056f);
    p = fmaf(p, f, 1.0f);
    return p * __int_as_float((n + 127) << 23);
}

// ================= setup =================
__global__ void setup_k(const int* __restrict__ mask) {
    int idx = threadIdx.x;
    if (idx < B_) {
        int s = 0;
        for (int t = 0; t < T_; t++) s += mask[idx * T_ + t];
        g_last[idx] = s - 1;
    }
    if (idx == B_) g_bar = 0u;
}

// ================= hi/lo bf16 conversion =================
__global__ void conv_k(const float* __restrict__ src, __nv_bfloat16* __restrict__ hi,
                       __nv_bfloat16* __restrict__ lo, long n4) {
    long i = (long)blockIdx.x * 256 + threadIdx.x;
    long stride = (long)gridDim.x * 256;
    for (; i < n4; i += stride) {
        float4 v = ((const float4*)src)[i];
        __nv_bfloat16 h0 = __float2bfloat16(v.x), h1 = __float2bfloat16(v.y);
        __nv_bfloat16 h2 = __float2bfloat16(v.z), h3 = __float2bfloat16(v.w);
        __nv_bfloat16 l0 = __float2bfloat16(v.x - __bfloat162float(h0));
        __nv_bfloat16 l1 = __float2bfloat16(v.y - __bfloat162float(h1));
        __nv_bfloat16 l2 = __float2bfloat16(v.z - __bfloat162float(h2));
        __nv_bfloat16 l3 = __float2bfloat16(v.w - __bfloat162float(h3));
        ((__nv_bfloat162*)hi)[i * 2 + 0] = __nv_bfloat162(h0, h1);
        ((__nv_bfloat162*)hi)[i * 2 + 1] = __nv_bfloat162(h2, h3);
        ((__nv_bfloat162*)lo)[i * 2 + 0] = __nv_bfloat162(l0, l1);
        ((__nv_bfloat162*)lo)[i * 2 + 1] = __nv_bfloat162(l2, l3);
    }
}

// build [emb(ids) || append] as hi/lo bf16, rows = MROWS, K = KX
__global__ void conv_gather(const int* __restrict__ ids, const float* __restrict__ emb,
                            const float* __restrict__ app,
                            __nv_bfloat16* __restrict__ hi, __nv_bfloat16* __restrict__ lo) {
    long total = (long)MROWS * (KX / 4);
    long i = (long)blockIdx.x * 256 + threadIdx.x;
    long stride = (long)gridDim.x * 256;
    for (; i < total; i += stride) {
        int m = (int)(i / (KX / 4));
        int q = (int)(i - (long)m * (KX / 4));
        int k = q * 4;
        const float* p;
        if (k < H_) p = emb + (long)ids[m] * H_ + k;
        else        p = app + (long)(m >> 7) * H_ + (k - H_);
        float4 v = *(const float4*)p;
        __nv_bfloat16 h0 = __float2bfloat16(v.x), h1 = __float2bfloat16(v.y);
        __nv_bfloat16 h2 = __float2bfloat16(v.z), h3 = __float2bfloat16(v.w);
        __nv_bfloat16 l0 = __float2bfloat16(v.x - __bfloat162float(h0));
        __nv_bfloat16 l1 = __float2bfloat16(v.y - __bfloat162float(h1));
        __nv_bfloat16 l2 = __float2bfloat16(v.z - __bfloat162float(h2));
        __nv_bfloat16 l3 = __float2bfloat16(v.w - __bfloat162float(h3));
        long o = (long)m * (KX / 2) + q * 2;
        ((__nv_bfloat162*)hi)[o + 0] = __nv_bfloat162(h0, h1);
        ((__nv_bfloat162*)hi)[o + 1] = __nv_bfloat162(h2, h3);
        ((__nv_bfloat162*)lo)[o + 0] = __nv_bfloat162(l0, l1);
        ((__nv_bfloat162*)lo)[o + 1] = __nv_bfloat162(l2, l3);
    }
}

// ================= HMMA GEMM (hi/lo 3-term): C[M,N] = A[M,K] @ B[N,K]^T + bias =================
#define LDSW 80                  // padded row stride in bytes (40 halves)
#define ATILE (128 * LDSW)       // 10240 B per matrix tile
#define HSTAGE (4 * ATILE)       // Ahi, Alo, Bhi, Blo
#define HSMEM (2 * HSTAGE)       // 81920 B, double buffered

__global__ __launch_bounds__(256, 1) void hmma_gemm(
    const __nv_bfloat16* __restrict__ Ah, const __nv_bfloat16* __restrict__ Al,
    const __nv_bfloat16* __restrict__ Bh, const __nv_bfloat16* __restrict__ Bl,
    const float* __restrict__ bias, float* __restrict__ C,
    int K, int Nvalid)
{
    extern __shared__ __align__(128) char smem[];
    uint32_t sb = smem_to_u32(smem);
    int tid = threadIdx.x;
    int lane = tid & 31, wid = tid >> 5;
    int wm = wid & 1, wn = wid >> 1;
    int n0 = blockIdx.x * 128;
    int m0 = blockIdx.y * 128;
    int NK = K >> 5;

    float acc[4][4][4];
#pragma unroll
    for (int a = 0; a < 4; a++)
#pragma unroll
        for (int b = 0; b < 4; b++)
#pragma unroll
            for (int c = 0; c < 4; c++) acc[a][b][c] = 0.0f;

    auto load_stage = [&](int stg) {
        int k0 = stg << 5;
        uint32_t db = sb + (stg & 1) * HSTAGE;
        int row = tid >> 2;
        int q   = tid & 3;
#pragma unroll
        for (int i = 0; i < 8; i++) {
            int mat = i >> 1;
            int r = (i & 1) * 64 + row;
            uint32_t dst = db + mat * ATILE + r * LDSW + q * 16;
            const __nv_bfloat16* src;
            uint32_t sz = 16;
            if (mat == 0)      src = Ah + (long)(m0 + r) * K + k0 + q * 8;
            else if (mat == 1) src = Al + (long)(m0 + r) * K + k0 + q * 8;
            else {
                int n = n0 + r;
                const __nv_bfloat16* base = (mat == 2) ? Bh : Bl;
                if (n >= Nvalid) { n = 0; sz = 0; }
                src = base + (long)n * K + k0 + q * 8;
            }
            cpasync16(dst, src, sz);
        }
    };

    load_stage(0);
    asm volatile("cp.async.commit_group;" ::: "memory");

    int a_row = lane & 15;
    int a_kh  = (lane >> 4) << 3;
    int b_g   = lane >> 3;
    int b_nr  = ((b_g >> 1) << 3) + (lane & 7);
    int b_kh  = (b_g & 1) << 3;

    for (int c = 0; c < NK; c++) {
        if (c + 1 < NK) {
            load_stage(c + 1);
            asm volatile("cp.async.commit_group;" ::: "memory");
            asm volatile("cp.async.wait_group 1;" ::: "memory");
        } else {
            asm volatile("cp.async.wait_group 0;" ::: "memory");
        }
        __syncthreads();

        uint32_t aB = sb + (c & 1) * HSTAGE;
#pragma unroll
        for (int kk = 0; kk < 32; kk += 16) {
            uint32_t bh[8], bl[8], af[16];
#pragma unroll
            for (int f2 = 0; f2 < 2; f2++) {
                uint32_t off = (uint32_t)((wn * 32 + f2 * 16 + b_nr) * LDSW + (kk + b_kh) * 2);
                ldm_x4(aB + 2 * ATILE + off, &bh[f2 * 4]);
                ldm_x4(aB + 3 * ATILE + off, &bl[f2 * 4]);
            }
#pragma unroll
            for (int fm = 0; fm < 4; fm++) {
                uint32_t off = (uint32_t)((wm * 64 + fm * 16 + a_row) * LDSW + (kk + a_kh) * 2);
                ldm_x4(aB + off, &af[fm * 4]);
            }
#pragma unroll
            for (int fm = 0; fm < 4; fm++)
#pragma unroll
                for (int fn = 0; fn < 4; fn++) {
                    mma16816(acc[fm][fn], &af[fm * 4], &bh[fn * 2]);
                    mma16816(acc[fm][fn], &af[fm * 4], &bl[fn * 2]);
                }
#pragma unroll
            for (int fm = 0; fm < 4; fm++) {
                uint32_t off = (uint32_t)((wm * 64 + fm * 16 + a_row) * LDSW + (kk + a_kh) * 2);
                ldm_x4(aB + ATILE + off, &af[fm * 4]);
            }
#pragma unroll
            for (int fm = 0; fm < 4; fm++)
#pragma unroll
                for (int fn = 0; fn < 4; fn++)
                    mma16816(acc[fm][fn], &af[fm * 4], &bh[fn * 2]);
        }
        __syncthreads();
    }

    int mbase = m0 + wm * 64 + (lane >> 2);
    int nbase = n0 + wn * 32 + ((lane & 3) << 1);
#pragma unroll
    for (int fm = 0; fm < 4; fm++) {
#pragma unroll
        for (int fn = 0; fn < 4; fn++) {
            int m = mbase + fm * 16;
            int n = nbase + fn * 8;
            float* d = acc[fm][fn];
            if (n < Nvalid) {
                float bv = bias[n];
                C[(long)m * Nvalid + n]       = d[0] + bv;
                C[(long)(m + 8) * Nvalid + n] = d[2] + bv;
            }
            if (n + 1 < Nvalid) {
                float bv = bias[n + 1];
                C[(long)m * Nvalid + n + 1]       = d[1] + bv;
                C[(long)(m + 8) * Nvalid + n + 1] = d[3] + bv;
            }
        }
    }
}

// ================= persistent LSTM recurrence =================
// 128 blocks x 192 threads (6 warps); warp w owns unit u = blk*6 + w.
// Cell state c lives in registers (lane b<16 holds c[b,u]). Grid barrier per step.
__global__ __launch_bounds__(192) void lstm_persist(
    const float* __restrict__ dh, const float* __restrict__ dctx,
    const float* __restrict__ Whh, const float* __restrict__ bhh,
    float* __restrict__ allh, float* __restrict__ selctx,
    __nv_bfloat16* __restrict__ ahi, __nv_bfloat16* __restrict__ alo)
{
    __shared__ __align__(16) float hs[B_ * H_];
    int tid = threadIdx.x, wid = tid >> 5, lane = tid & 31;
    int u = blockIdx.x * LSTM_WARPS + wid;

    const float4* wp0 = (const float4*)(Whh + (long)(0 * H_ + u) * H_);
    const float4* wp1 = (const float4*)(Whh + (long)(1 * H_ + u) * H_);
    const float4* wp2 = (const float4*)(Whh + (long)(2 * H_ + u) * H_);
    const float4* wp3 = (const float4*)(Whh + (long)(3 * H_ + u) * H_);
    const float4* h4 = (const float4*)hs;

    float creg = 0.0f, b0r = 0.0f, b1r = 0.0f, b2r = 0.0f, b3r = 0.0f;
    int lastb = 0;
    if (lane < 16) {
        creg = dctx[lane * H_ + u];
        lastb = g_last[lane];
        b0r = bhh[0 * H_ + u]; b1r = bhh[1 * H_ + u];
        b2r = bhh[2 * H_ + u]; b3r = bhh[3 * H_ + u];
    }

    for (int t = 0; t < T_; t++) {
        if (t == 0) {
            for (int i4 = tid; i4 < B_ * H_ / 4; i4 += 192)
                ((float4*)hs)[i4] = __ldcg((const float4*)dh + i4);
        } else {
            for (int i4 = tid; i4 < B_ * H_ / 4; i4 += 192) {
                int b = i4 / (H_ / 4), q = i4 - b * (H_ / 4);
                ((float4*)hs)[i4] = __ldcg((const float4*)(allh + ((long)b * T_ + t - 1) * H_) + q);
            }
        }
        __syncthreads();

        float acc[4][16];
#pragma unroll
        for (int g = 0; g < 4; g++)
#pragma unroll
            for (int b = 0; b < 16; b++) acc[g][b] = 0.0f;

#pragma unroll
        for (int ch = 0; ch < 6; ch++) {
            int k4 = ch * 32 + lane;
            float4 w0 = wp0[k4], w1 = wp1[k4], w2 = wp2[k4], w3 = wp3[k4];
#pragma unroll
            for (int b = 0; b < 16; b++) {
                float4 h = h4[b * 192 + k4];
                acc[0][b] = fmaf(w0.x, h.x, fmaf(w0.y, h.y, fmaf(w0.z, h.z, fmaf(w0.w, h.w, acc[0][b]))));
                acc[1][b] = fmaf(w1.x, h.x, fmaf(w1.y, h.y, fmaf(w1.z, h.z, fmaf(w1.w, h.w, acc[1][b]))));
                acc[2][b] = fmaf(w2.x, h.x, fmaf(w2.y, h.y, fmaf(w2.z, h.z, fmaf(w2.w, h.w, acc[2][b]))));
                acc[3][b] = fmaf(w3.x, h.x, fmaf(w3.y, h.y, fmaf(w3.z, h.z, fmaf(w3.w, h.w, acc[3][b]))));
            }
        }
#pragma unroll
        for (int g = 0; g < 4; g++)
#pragma unroll
            for (int b = 0; b < 16; b++) {
                float v = acc[g][b];
#pragma unroll
                for (int off = 16; off; off >>= 1) v += __shfl_xor_sync(0xffffffffu, v, off);
                acc[g][b] = v;
            }

        if (lane < 16) {
            int b = lane;
            long m = (long)b * T_ + t;
            const float* xr = g_xg + m * G_;
            float xi = acc[0][b] + xr[0 * H_ + u] + b0r;
            float xf = acc[1][b] + xr[1 * H_ + u] + b1r;
            float xg = acc[2][b] + xr[2 * H_ + u] + b2r;
            float xo = acc[3][b] + xr[3 * H_ + u] + b3r;
            float si = 1.0f / (1.0f + expf(-xi));
            float sf = 1.0f / (1.0f + expf(-xf));
            float so = 1.0f / (1.0f + expf(-xo));
            float tg = tanhf(xg);
            creg = sf * creg + si * tg;
            float h = so * tanhf(creg);
            allh[m * H_ + u] = h;
            __nv_bfloat16 hh = __float2bfloat16(h);
            ahi[m * H_ + u] = hh;
            alo[m * H_ + u] = __float2bfloat16(h - __bfloat162float(hh));
            if (t == lastb) selctx[b * H_ + u] = creg;
        }

        if (t + 1 < T_) {
            __threadfence();
            __syncthreads();
            if (tid == 0) {
                atomicAdd(&g_bar, 1u);
                unsigned tgt = (unsigned)(LSTM_BLOCKS * (t + 1));
                while (ld_acq(&g_bar) < tgt) { }
            }
            __syncthreads();
        }
    }
}

// ================= fused log-softmax =================
__global__ void softmax_k(float* __restrict__ lp) {
    __shared__ float red[256];
    int m = blockIdx.x;
    int tid = threadIdx.x;
    float* row = lp + (long)m * V_;
    float mx = -1e30f;
    for (int j = tid; j < V_; j += 256) mx = fmaxf(mx, row[j]);
    red[tid] = mx; __syncthreads();
    for (int s = 128; s; s >>= 1) { if (tid < s) red[tid] = fmaxf(red[tid], red[tid + s]); __syncthreads(); }
    mx = red[0];
    __syncthreads();
    float sum = 0.0f;
    for (int j = tid; j < V_; j += 256) sum += fexp(row[j] - mx);
    red[tid] = sum; __syncthreads();
    for (int s = 128; s; s >>= 1) { if (tid < s) red[tid] += red[tid + s]; __syncthreads(); }
    float l = mx + logf(red[0]);
    __syncthreads();
    for (int j = tid; j < V_; j += 256) row[j] -= l;
}

// ================= launch =================
extern "C" void kernel_launch(void* const* d_in, const int* in_sizes, int n_in,
                              void* d_out, int out_size)
{
    const int*   ids  = (const int*)d_in[0];
    const int*   mask = (const int*)d_in[1];
    const float* dh   = (const float*)d_in[2];
    const float* dc   = (const float*)d_in[3];
    const float* dapp = (const float*)d_in[4];
    const float* emb  = (const float*)d_in[5];
    const float* Wih  = (const float*)d_in[6];
    const float* Whh  = (const float*)d_in[7];
    const float* bih  = (const float*)d_in[8];
    const float* bhh  = (const float*)d_in[9];
    const float* lmw  = (const float*)d_in[10];
    const float* lmb  = (const float*)d_in[11];
    (void)in_sizes; (void)n_in; (void)out_size;

    float* out    = (float*)d_out;
    float* allh   = out;
    float* selctx = out + (long)MROWS * H_;
    float* lp     = selctx + B_ * H_;

    static int attr_set = 0;
    if (!attr_set) {
        cudaFuncSetAttribute(hmma_gemm, cudaFuncAttributeMaxDynamicSharedMemorySize, HSMEM);
        attr_set = 1;
    }

    __nv_bfloat16 *whi, *wlo, *ahi, *alo, *xah, *xal, *wihh, *wihl;
    float* xg;
    cudaGetSymbolAddress((void**)&whi, g_whi);
    cudaGetSymbolAddress((void**)&wlo, g_wlo);
    cudaGetSymbolAddress((void**)&ahi, g_ahi);
    cudaGetSymbolAddress((void**)&alo, g_alo);
    cudaGetSymbolAddress((void**)&xah, g_xah);
    cudaGetSymbolAddress((void**)&xal, g_xal);
    cudaGetSymbolAddress((void**)&wihh, g_wihh);
    cudaGetSymbolAddress((void**)&wihl, g_wihl);
    cudaGetSymbolAddress((void**)&xg, g_xg);

    setup_k<<<1, 32>>>(mask);

    conv_gather<<<1024, 256>>>(ids, emb, dapp, xah, xal);
    conv_k<<<1024, 256>>>(Wih, wihh, wihl, (long)G_ * KX / 4);

    hmma_gemm<<<dim3(G_ / 128, MROWS / 128), 256, HSMEM>>>(
        xah, xal, wihh, wihl, bih, xg, KX, G_);

    conv_k<<<4096, 256>>>(lmw, whi, wlo, (long)V_ * H_ / 4);

    lstm_persist<<<LSTM_BLOCKS, 192>>>(dh, dc, Whh, bhh, allh, selctx, ahi, alo);

    hmma_gemm<<<dim3((V_ + 127) / 128, MROWS / 128), 256, HSMEM>>>(
        ahi, alo, whi, wlo, lmb, lp, H_, V_);

    softmax_k<<<MROWS, 256>>>(lp);
}

// round 10
// speedup vs baseline: 1.9573x; 1.0016x over previous
#include <cuda_runtime.h>
#include <cuda_bf16.h>
#include <cstdint>

#define V_  50257
#define H_  768
#define B_  16
#define T_  128
#define G_  3072          // 4*H
#define KX  1536          // 2*H
#define MROWS 2048        // B*T

#define LSTM_BLOCKS 128
#define LSTM_WARPS  6     // units per block; 128*6 = 768 = H_

// ================= scratch (no cudaMalloc allowed) =================
__device__ float g_xg[(long)MROWS * G_];                 // input-side gate projections
__device__ float g_lse[MROWS];
__device__ int   g_last[B_];
__device__ unsigned g_bar;                               // grid barrier counter
__device__ __nv_bfloat16 g_whi[(long)V_ * H_];           // lm_w hi
__device__ __nv_bfloat16 g_wlo[(long)V_ * H_];           // lm_w lo
__device__ __nv_bfloat16 g_ahi[(long)MROWS * H_];        // hiddens hi
__device__ __nv_bfloat16 g_alo[(long)MROWS * H_];        // hiddens lo
__device__ __nv_bfloat16 g_xah[(long)MROWS * KX];        // [emb||app] hi
__device__ __nv_bfloat16 g_xal[(long)MROWS * KX];        // [emb||app] lo
__device__ __nv_bfloat16 g_wihh[(long)G_ * KX];          // W_ih hi
__device__ __nv_bfloat16 g_wihl[(long)G_ * KX];          // W_ih lo

// ================= small ptx helpers (baseline PTX only) =================
__device__ __forceinline__ uint32_t smem_to_u32(const void* p) {
    uint32_t a;
    asm("{ .reg .u64 t; cvta.to.shared.u64 t, %1; cvt.u32.u64 %0, t; }" : "=r"(a) : "l"(p));
    return a;
}
__device__ __forceinline__ void cpasync16(uint32_t dst, const void* src, uint32_t sz) {
    asm volatile("cp.async.cg.shared.global [%0], [%1], 16, %2;\n"
        :: "r"(dst), "l"(src), "r"(sz) : "memory");
}
__device__ __forceinline__ void ldm_x4(uint32_t addr, uint32_t* r) {
    asm volatile("ldmatrix.sync.aligned.m8n8.x4.shared.b16 {%0,%1,%2,%3}, [%4];"
        : "=r"(r[0]), "=r"(r[1]), "=r"(r[2]), "=r"(r[3]) : "r"(addr));
}
__device__ __forceinline__ void mma16816(float* d, const uint32_t* a, const uint32_t* b) {
    asm volatile("mma.sync.aligned.m16n8k16.row.col.f32.bf16.bf16.f32 "
        "{%0,%1,%2,%3}, {%4,%5,%6,%7}, {%8,%9}, {%0,%1,%2,%3};"
        : "+f"(d[0]), "+f"(d[1]), "+f"(d[2]), "+f"(d[3])
        : "r"(a[0]), "r"(a[1]), "r"(a[2]), "r"(a[3]), "r"(b[0]), "r"(b[1]));
}
__device__ __forceinline__ unsigned ld_acq(const unsigned* p) {
    unsigned v;
    asm volatile("ld.acquire.gpu.global.u32 %0, [%1];" : "=r"(v) : "l"(p) : "memory");
    return v;
}

// ================= fast exp =================
__device__ __forceinline__ float fexp(float x) {
    x = fmaxf(x, -20.0f);
    float t  = x * 1.4426950408889634f;
    float z  = t + 12582912.0f;
    float nf = z - 12582912.0f;
    float f  = t - nf;
    int   n  = (int)nf;
    float p = fmaf(0.00133335581f, f, 0.00961812911f);
    p = fmaf(p, f, 0.0555041087f);
    p = fmaf(p, f, 0.240226507f);
    p = fmaf(p, f, 0.69314718056f);
    p = fmaf(p, f, 1.0f);
    return p * __int_as_float((n + 127) << 23);
}

// ================= setup =================
__global__ void setup_k(const int* __restrict__ mask) {
    int idx = threadIdx.x;
    if (idx < B_) {
        int s = 0;
        for (int t = 0; t < T_; t++) s += mask[idx * T_ + t];
        g_last[idx] = s - 1;
    }
    if (idx == B_) g_bar = 0u;
}

// ================= hi/lo bf16 conversion =================
__global__ void conv_k(const float* __restrict__ src, __nv_bfloat16* __restrict__ hi,
                       __nv_bfloat16* __restrict__ lo, long n4) {
    long i = (long)blockIdx.x * 256 + threadIdx.x;
    long stride = (long)gridDim.x * 256;
    for (; i < n4; i += stride) {
        float4 v = ((const float4*)src)[i];
        __nv_bfloat16 h0 = __float2bfloat16(v.x), h1 = __float2bfloat16(v.y);
        __nv_bfloat16 h2 = __float2bfloat16(v.z), h3 = __float2bfloat16(v.w);
        __nv_bfloat16 l0 = __float2bfloat16(v.x - __bfloat162float(h0));
        __nv_bfloat16 l1 = __float2bfloat16(v.y - __bfloat162float(h1));
        __nv_bfloat16 l2 = __float2bfloat16(v.z - __bfloat162float(h2));
        __nv_bfloat16 l3 = __float2bfloat16(v.w - __bfloat162float(h3));
        ((__nv_bfloat162*)hi)[i * 2 + 0] = __nv_bfloat162(h0, h1);
        ((__nv_bfloat162*)hi)[i * 2 + 1] = __nv_bfloat162(h2, h3);
        ((__nv_bfloat162*)lo)[i * 2 + 0] = __nv_bfloat162(l0, l1);
        ((__nv_bfloat162*)lo)[i * 2 + 1] = __nv_bfloat162(l2, l3);
    }
}

// build [emb(ids) || append] as hi/lo bf16, rows = MROWS, K = KX
__global__ void conv_gather(const int* __restrict__ ids, const float* __restrict__ emb,
                            const float* __restrict__ app,
                            __nv_bfloat16* __restrict__ hi, __nv_bfloat16* __restrict__ lo) {
    long total = (long)MROWS * (KX / 4);
    long i = (long)blockIdx.x * 256 + threadIdx.x;
    long stride = (long)gridDim.x * 256;
    for (; i < total; i += stride) {
        int m = (int)(i / (KX / 4));
        int q = (int)(i - (long)m * (KX / 4));
        int k = q * 4;
        const float* p;
        if (k < H_) p = emb + (long)ids[m] * H_ + k;
        else        p = app + (long)(m >> 7) * H_ + (k - H_);
        float4 v = *(const float4*)p;
        __nv_bfloat16 h0 = __float2bfloat16(v.x), h1 = __float2bfloat16(v.y);
        __nv_bfloat16 h2 = __float2bfloat16(v.z), h3 = __float2bfloat16(v.w);
        __nv_bfloat16 l0 = __float2bfloat16(v.x - __bfloat162float(h0));
        __nv_bfloat16 l1 = __float2bfloat16(v.y - __bfloat162float(h1));
        __nv_bfloat16 l2 = __float2bfloat16(v.z - __bfloat162float(h2));
        __nv_bfloat16 l3 = __float2bfloat16(v.w - __bfloat162float(h3));
        long o = (long)m * (KX / 2) + q * 2;
        ((__nv_bfloat162*)hi)[o + 0] = __nv_bfloat162(h0, h1);
        ((__nv_bfloat162*)hi)[o + 1] = __nv_bfloat162(h2, h3);
        ((__nv_bfloat162*)lo)[o + 0] = __nv_bfloat162(l0, l1);
        ((__nv_bfloat162*)lo)[o + 1] = __nv_bfloat162(l2, l3);
    }
}

// ================= HMMA GEMM (hi/lo 3-term): C[M,N] = A[M,K] @ B[N,K]^T + bias =================
#define LDSW 80                  // padded row stride in bytes (40 halves)
#define ATILE (128 * LDSW)       // 10240 B per matrix tile
#define HSTAGE (4 * ATILE)       // Ahi, Alo, Bhi, Blo
#define HSMEM (2 * HSTAGE)       // 81920 B, double buffered

__global__ __launch_bounds__(256, 1) void hmma_gemm(
    const __nv_bfloat16* __restrict__ Ah, const __nv_bfloat16* __restrict__ Al,
    const __nv_bfloat16* __restrict__ Bh, const __nv_bfloat16* __restrict__ Bl,
    const float* __restrict__ bias, float* __restrict__ C,
    int K, int Nvalid)
{
    extern __shared__ __align__(128) char smem[];
    uint32_t sb = smem_to_u32(smem);
    int tid = threadIdx.x;
    int lane = tid & 31, wid = tid >> 5;
    int wm = wid & 1, wn = wid >> 1;
    int n0 = blockIdx.x * 128;
    int m0 = blockIdx.y * 128;
    int NK = K >> 5;

    float acc[4][4][4];
#pragma unroll
    for (int a = 0; a < 4; a++)
#pragma unroll
        for (int b = 0; b < 4; b++)
#pragma unroll
            for (int c = 0; c < 4; c++) acc[a][b][c] = 0.0f;

    auto load_stage = [&](int stg) {
        int k0 = stg << 5;
        uint32_t db = sb + (stg & 1) * HSTAGE;
        int row = tid >> 2;
        int q   = tid & 3;
#pragma unroll
        for (int i = 0; i < 8; i++) {
            int mat = i >> 1;
            int r = (i & 1) * 64 + row;
            uint32_t dst = db + mat * ATILE + r * LDSW + q * 16;
            const __nv_bfloat16* src;
            uint32_t sz = 16;
            if (mat == 0)      src = Ah + (long)(m0 + r) * K + k0 + q * 8;
            else if (mat == 1) src = Al + (long)(m0 + r) * K + k0 + q * 8;
            else {
                int n = n0 + r;
                const __nv_bfloat16* base = (mat == 2) ? Bh : Bl;
                if (n >= Nvalid) { n = 0; sz = 0; }
                src = base + (long)n * K + k0 + q * 8;
            }
            cpasync16(dst, src, sz);
        }
    };

    load_stage(0);
    asm volatile("cp.async.commit_group;" ::: "memory");

    int a_row = lane & 15;
    int a_kh  = (lane >> 4) << 3;
    int b_g   = lane >> 3;
    int b_nr  = ((b_g >> 1) << 3) + (lane & 7);
    int b_kh  = (b_g & 1) << 3;

    for (int c = 0; c < NK; c++) {
        if (c + 1 < NK) {
            load_stage(c + 1);
            asm volatile("cp.async.commit_group;" ::: "memory");
            asm volatile("cp.async.wait_group 1;" ::: "memory");
        } else {
            asm volatile("cp.async.wait_group 0;" ::: "memory");
        }
        __syncthreads();

        uint32_t aB = sb + (c & 1) * HSTAGE;
#pragma unroll
        for (int kk = 0; kk < 32; kk += 16) {
            uint32_t bh[8], bl[8], af[16];
#pragma unroll
            for (int f2 = 0; f2 < 2; f2++) {
                uint32_t off = (uint32_t)((wn * 32 + f2 * 16 + b_nr) * LDSW + (kk + b_kh) * 2);
                ldm_x4(aB + 2 * ATILE + off, &bh[f2 * 4]);
                ldm_x4(aB + 3 * ATILE + off, &bl[f2 * 4]);
            }
#pragma unroll
            for (int fm = 0; fm < 4; fm++) {
                uint32_t off = (uint32_t)((wm * 64 + fm * 16 + a_row) * LDSW + (kk + a_kh) * 2);
                ldm_x4(aB + off, &af[fm * 4]);
            }
#pragma unroll
            for (int fm = 0; fm < 4; fm++)
#pragma unroll
                for (int fn = 0; fn < 4; fn++) {
                    mma16816(acc[fm][fn], &af[fm * 4], &bh[fn * 2]);
                    mma16816(acc[fm][fn], &af[fm * 4], &bl[fn * 2]);
                }
#pragma unroll
            for (int fm = 0; fm < 4; fm++) {
                uint32_t off = (uint32_t)((wm * 64 + fm * 16 + a_row) * LDSW + (kk + a_kh) * 2);
                ldm_x4(aB + ATILE + off, &af[fm * 4]);
            }
#pragma unroll
            for (int fm = 0; fm < 4; fm++)
#pragma unroll
                for (int fn = 0; fn < 4; fn++)
                    mma16816(acc[fm][fn], &af[fm * 4], &bh[fn * 2]);
        }
        __syncthreads();
    }

    int mbase = m0 + wm * 64 + (lane >> 2);
    int nbase = n0 + wn * 32 + ((lane & 3) << 1);
#pragma unroll
    for (int fm = 0; fm < 4; fm++) {
#pragma unroll
        for (int fn = 0; fn < 4; fn++) {
            int m = mbase + fm * 16;
            int n = nbase + fn * 8;
            float* d = acc[fm][fn];
            if (n < Nvalid) {
                float bv = bias[n];
                C[(long)m * Nvalid + n]       = d[0] + bv;
                C[(long)(m + 8) * Nvalid + n] = d[2] + bv;
            }
            if (n + 1 < Nvalid) {
                float bv = bias[n + 1];
                C[(long)m * Nvalid + n + 1]       = d[1] + bv;
                C[(long)(m + 8) * Nvalid + n + 1] = d[3] + bv;
            }
        }
    }
}

// ================= persistent LSTM recurrence =================
// 128 blocks x 192 threads (6 warps); warp w owns unit u = blk*6 + w.
// Cell state c lives in registers (lane b<16 holds c[b,u]). Grid barrier per step.
__global__ __launch_bounds__(192) void lstm_persist(
    const float* __restrict__ dh, const float* __restrict__ dctx,
    const float* __restrict__ Whh, const float* __restrict__ bhh,
    float* __restrict__ allh, float* __restrict__ selctx,
    __nv_bfloat16* __restrict__ ahi, __nv_bfloat16* __restrict__ alo)
{
    __shared__ __align__(16) float hs[B_ * H_];
    int tid = threadIdx.x, wid = tid >> 5, lane = tid & 31;
    int u = blockIdx.x * LSTM_WARPS + wid;

    const float4* wp0 = (const float4*)(Whh + (long)(0 * H_ + u) * H_);
    const float4* wp1 = (const float4*)(Whh + (long)(1 * H_ + u) * H_);
    const float4* wp2 = (const float4*)(Whh + (long)(2 * H_ + u) * H_);
    const float4* wp3 = (const float4*)(Whh + (long)(3 * H_ + u) * H_);
    const float4* h4 = (const float4*)hs;

    float creg = 0.0f, b0r = 0.0f, b1r = 0.0f, b2r = 0.0f, b3r = 0.0f;
    int lastb = 0;
    if (lane < 16) {
        creg = dctx[lane * H_ + u];
        lastb = g_last[lane];
        b0r = bhh[0 * H_ + u]; b1r = bhh[1 * H_ + u];
        b2r = bhh[2 * H_ + u]; b3r = bhh[3 * H_ + u];
    }

    for (int t = 0; t < T_; t++) {
        if (t == 0) {
            for (int i4 = tid; i4 < B_ * H_ / 4; i4 += 192)
                ((float4*)hs)[i4] = __ldcg((const float4*)dh + i4);
        } else {
            for (int i4 = tid; i4 < B_ * H_ / 4; i4 += 192) {
                int b = i4 / (H_ / 4), q = i4 - b * (H_ / 4);
                ((float4*)hs)[i4] = __ldcg((const float4*)(allh + ((long)b * T_ + t - 1) * H_) + q);
            }
        }
        __syncthreads();

        float acc[4][16];
#pragma unroll
        for (int g = 0; g < 4; g++)
#pragma unroll
            for (int b = 0; b < 16; b++) acc[g][b] = 0.0f;

#pragma unroll
        for (int ch = 0; ch < 6; ch++) {
            int k4 = ch * 32 + lane;
            float4 w0 = wp0[k4], w1 = wp1[k4], w2 = wp2[k4], w3 = wp3[k4];
#pragma unroll
            for (int b = 0; b < 16; b++) {
                float4 h = h4[b * 192 + k4];
                acc[0][b] = fmaf(w0.x, h.x, fmaf(w0.y, h.y, fmaf(w0.z, h.z, fmaf(w0.w, h.w, acc[0][b]))));
                acc[1][b] = fmaf(w1.x, h.x, fmaf(w1.y, h.y, fmaf(w1.z, h.z, fmaf(w1.w, h.w, acc[1][b]))));
                acc[2][b] = fmaf(w2.x, h.x, fmaf(w2.y, h.y, fmaf(w2.z, h.z, fmaf(w2.w, h.w, acc[2][b]))));
                acc[3][b] = fmaf(w3.x, h.x, fmaf(w3.y, h.y, fmaf(w3.z, h.z, fmaf(w3.w, h.w, acc[3][b]))));
            }
        }
#pragma unroll
        for (int g = 0; g < 4; g++)
#pragma unroll
            for (int b = 0; b < 16; b++) {
                float v = acc[g][b];
#pragma unroll
                for (int off = 16; off; off >>= 1) v += __shfl_xor_sync(0xffffffffu, v, off);
                acc[g][b] = v;
            }

        if (lane < 16) {
            int b = lane;
            long m = (long)b * T_ + t;
            const float* xr = g_xg + m * G_;
            float xi = acc[0][b] + xr[0 * H_ + u] + b0r;
            float xf = acc[1][b] + xr[1 * H_ + u] + b1r;
            float xg = acc[2][b] + xr[2 * H_ + u] + b2r;
            float xo = acc[3][b] + xr[3 * H_ + u] + b3r;
            float si = 1.0f / (1.0f + expf(-xi));
            float sf = 1.0f / (1.0f + expf(-xf));
            float so = 1.0f / (1.0f + expf(-xo));
            float tg = tanhf(xg);
            creg = sf * creg + si * tg;
            float h = so * tanhf(creg);
            allh[m * H_ + u] = h;
            __nv_bfloat16 hh = __float2bfloat16(h);
            ahi[m * H_ + u] = hh;
            alo[m * H_ + u] = __float2bfloat16(h - __bfloat162float(hh));
            if (t == lastb) selctx[b * H_ + u] = creg;
        }

        if (t + 1 < T_) {
            __threadfence();
            __syncthreads();
            if (tid == 0) {
                atomicAdd(&g_bar, 1u);
                unsigned tgt = (unsigned)(LSTM_BLOCKS * (t + 1));
                while (ld_acq(&g_bar) < tgt) { }
            }
            __syncthreads();
        }
    }
}

// ================= fused log-softmax =================
__global__ void softmax_k(float* __restrict__ lp) {
    __shared__ float red[256];
    int m = blockIdx.x;
    int tid = threadIdx.x;
    float* row = lp + (long)m * V_;
    float mx = -1e30f;
    for (int j = tid; j < V_; j += 256) mx = fmaxf(mx, row[j]);
    red[tid] = mx; __syncthreads();
    for (int s = 128; s; s >>= 1) { if (tid < s) red[tid] = fmaxf(red[tid], red[tid + s]); __syncthreads(); }
    mx = red[0];
    __syncthreads();
    float sum = 0.0f;
    for (int j = tid; j < V_; j += 256) sum += fexp(row[j] - mx);
    red[tid] = sum; __syncthreads();
    for (int s = 128; s; s >>= 1) { if (tid < s) red[tid] += red[tid + s]; __syncthreads(); }
    float l = mx + logf(red[0]);
    __syncthreads();
    for (int j = tid; j < V_; j += 256) row[j] -= l;
}

// ================= launch =================
extern "C" void kernel_launch(void* const* d_in, const int* in_sizes, int n_in,
                              void* d_out, int out_size)
{
    const int*   ids  = (const int*)d_in[0];
    const int*   mask = (const int*)d_in[1];
    const float* dh   = (const float*)d_in[2];
    const float* dc   = (const float*)d_in[3];
    const float* dapp = (const float*)d_in[4];
    const float* emb  = (const float*)d_in[5];
    const float* Wih  = (const float*)d_in[6];
    const float* Whh  = (const float*)d_in[7];
    const float* bih  = (const float*)d_in[8];
    const float* bhh  = (const float*)d_in[9];
    const float* lmw  = (const float*)d_in[10];
    const float* lmb  = (const float*)d_in[11];
    (void)in_sizes; (void)n_in; (void)out_size;

    float* out    = (float*)d_out;
    float* allh   = out;
    float* selctx = out + (long)MROWS * H_;
    float* lp     = selctx + B_ * H_;

    static int attr_set = 0;
    if (!attr_set) {
        cudaFuncSetAttribute(hmma_gemm, cudaFuncAttributeMaxDynamicSharedMemorySize, HSMEM);
        attr_set = 1;
    }

    __nv_bfloat16 *whi, *wlo, *ahi, *alo, *xah, *xal, *wihh, *wihl;
    float* xg;
    cudaGetSymbolAddress((void**)&whi, g_whi);
    cudaGetSymbolAddress((void**)&wlo, g_wlo);
    cudaGetSymbolAddress((void**)&ahi, g_ahi);
    cudaGetSymbolAddress((void**)&alo, g_alo);
    cudaGetSymbolAddress((void**)&xah, g_xah);
    cudaGetSymbolAddress((void**)&xal, g_xal);
    cudaGetSymbolAddress((void**)&wihh, g_wihh);
    cudaGetSymbolAddress((void**)&wihl, g_wihl);
    cudaGetSymbolAddress((void**)&xg, g_xg);

    setup_k<<<1, 32>>>(mask);

    conv_gather<<<1024, 256>>>(ids, emb, dapp, xah, xal);
    conv_k<<<1024, 256>>>(Wih, wihh, wihl, (long)G_ * KX / 4);

    hmma_gemm<<<dim3(G_ / 128, MROWS / 128), 256, HSMEM>>>(
        xah, xal, wihh, wihl, bih, xg, KX, G_);

    conv_k<<<4096, 256>>>(lmw, whi, wlo, (long)V_ * H_ / 4);

    lstm_persist<<<LSTM_BLOCKS, 192>>>(dh, dc, Whh, bhh, allh, selctx, ahi, alo);

    hmma_gemm<<<dim3((V_ + 127) / 128, MROWS / 128), 256, HSMEM>>>(
        ahi, alo, whi, wlo, lmb, lp, H_, V_);

    softmax_k<<<MROWS, 256>>>(lp);
}

// round 11
// speedup vs baseline: 1.9916x; 1.0175x over previous
#include <cuda_runtime.h>
#include <cuda_bf16.h>
#include <cstdint>

#define V_  50257
#define H_  768
#define B_  16
#define T_  128
#define G_  3072          // 4*H
#define KX  1536          // 2*H
#define MROWS 2048        // B*T

#define LSTM_BLOCKS 128
#define LSTM_WARPS  6     // units per block; 128*6 = 768 = H_

// ================= scratch (no cudaMalloc allowed) =================
__device__ float g_xg[(long)MROWS * G_];                 // input-side gate projections
__device__ int   g_last[B_];
__device__ unsigned g_bar;                               // grid barrier counter
__device__ __nv_bfloat16 g_whi[(long)V_ * H_];           // lm_w hi
__device__ __nv_bfloat16 g_wlo[(long)V_ * H_];           // lm_w lo
__device__ __nv_bfloat16 g_ahi[(long)MROWS * H_];        // hiddens hi
__device__ __nv_bfloat16 g_alo[(long)MROWS * H_];        // hiddens lo
__device__ __nv_bfloat16 g_xah[(long)MROWS * KX];        // [emb||app] hi
__device__ __nv_bfloat16 g_xal[(long)MROWS * KX];        // [emb||app] lo
__device__ __nv_bfloat16 g_wihh[(long)G_ * KX];          // W_ih hi
__device__ __nv_bfloat16 g_wihl[(long)G_ * KX];          // W_ih lo

// ================= small ptx helpers (baseline PTX only) =================
__device__ __forceinline__ uint32_t smem_to_u32(const void* p) {
    uint32_t a;
    asm("{ .reg .u64 t; cvta.to.shared.u64 t, %1; cvt.u32.u64 %0, t; }" : "=r"(a) : "l"(p));
    return a;
}
__device__ __forceinline__ void cpasync16(uint32_t dst, const void* src, uint32_t sz) {
    asm volatile("cp.async.cg.shared.global [%0], [%1], 16, %2;\n"
        :: "r"(dst), "l"(src), "r"(sz) : "memory");
}
__device__ __forceinline__ void ldm_x4(uint32_t addr, uint32_t* r) {
    asm volatile("ldmatrix.sync.aligned.m8n8.x4.shared.b16 {%0,%1,%2,%3}, [%4];"
        : "=r"(r[0]), "=r"(r[1]), "=r"(r[2]), "=r"(r[3]) : "r"(addr));
}
__device__ __forceinline__ void mma16816(float* d, const uint32_t* a, const uint32_t* b) {
    asm volatile("mma.sync.aligned.m16n8k16.row.col.f32.bf16.bf16.f32 "
        "{%0,%1,%2,%3}, {%4,%5,%6,%7}, {%8,%9}, {%0,%1,%2,%3};"
        : "+f"(d[0]), "+f"(d[1]), "+f"(d[2]), "+f"(d[3])
        : "r"(a[0]), "r"(a[1]), "r"(a[2]), "r"(a[3]), "r"(b[0]), "r"(b[1]));
}
__device__ __forceinline__ unsigned ld_acq(const unsigned* p) {
    unsigned v;
    asm volatile("ld.acquire.gpu.global.u32 %0, [%1];" : "=r"(v) : "l"(p) : "memory");
    return v;
}

// ================= fast exp =================
__device__ __forceinline__ float fexp(float x) {
    x = fmaxf(x, -20.0f);
    float t  = x * 1.4426950408889634f;
    float z  = t + 12582912.0f;
    float nf = z - 12582912.0f;
    float f  = t - nf;
    int   n  = (int)nf;
    float p = fmaf(0.00133335581f, f, 0.00961812911f);
    p = fmaf(p, f, 0.0555041087f);
    p = fmaf(p, f, 0.240226507f);
    p = fmaf(p, f, 0.69314718056f);
    p = fmaf(p, f, 1.0f);
    return p * __int_as_float((n + 127) << 23);
}

// ================= setup =================
__global__ void setup_k(const int* __restrict__ mask) {
    int idx = threadIdx.x;
    if (idx < B_) {
        int s = 0;
        for (int t = 0; t < T_; t++) s += mask[idx * T_ + t];
        g_last[idx] = s - 1;
    }
    if (idx == B_) g_bar = 0u;
}

// ================= hi/lo bf16 conversion =================
__global__ void conv_k(const float* __restrict__ src, __nv_bfloat16* __restrict__ hi,
                       __nv_bfloat16* __restrict__ lo, long n4) {
    long i = (long)blockIdx.x * 256 + threadIdx.x;
    long stride = (long)gridDim.x * 256;
    for (; i < n4; i += stride) {
        float4 v = ((const float4*)src)[i];
        __nv_bfloat16 h0 = __float2bfloat16(v.x), h1 = __float2bfloat16(v.y);
        __nv_bfloat16 h2 = __float2bfloat16(v.z), h3 = __float2bfloat16(v.w);
        __nv_bfloat16 l0 = __float2bfloat16(v.x - __bfloat162float(h0));
        __nv_bfloat16 l1 = __float2bfloat16(v.y - __bfloat162float(h1));
        __nv_bfloat16 l2 = __float2bfloat16(v.z - __bfloat162float(h2));
        __nv_bfloat16 l3 = __float2bfloat16(v.w - __bfloat162float(h3));
        ((__nv_bfloat162*)hi)[i * 2 + 0] = __nv_bfloat162(h0, h1);
        ((__nv_bfloat162*)hi)[i * 2 + 1] = __nv_bfloat162(h2, h3);
        ((__nv_bfloat162*)lo)[i * 2 + 0] = __nv_bfloat162(l0, l1);
        ((__nv_bfloat162*)lo)[i * 2 + 1] = __nv_bfloat162(l2, l3);
    }
}

// build [emb(ids) || append] as hi/lo bf16, rows = MROWS, K = KX
__global__ void conv_gather(const int* __restrict__ ids, const float* __restrict__ emb,
                            const float* __restrict__ app,
                            __nv_bfloat16* __restrict__ hi, __nv_bfloat16* __restrict__ lo) {
    long total = (long)MROWS * (KX / 4);
    long i = (long)blockIdx.x * 256 + threadIdx.x;
    long stride = (long)gridDim.x * 256;
    for (; i < total; i += stride) {
        int m = (int)(i / (KX / 4));
        int q = (int)(i - (long)m * (KX / 4));
        int k = q * 4;
        const float* p;
        if (k < H_) p = emb + (long)ids[m] * H_ + k;
        else        p = app + (long)(m >> 7) * H_ + (k - H_);
        float4 v = *(const float4*)p;
        __nv_bfloat16 h0 = __float2bfloat16(v.x), h1 = __float2bfloat16(v.y);
        __nv_bfloat16 h2 = __float2bfloat16(v.z), h3 = __float2bfloat16(v.w);
        __nv_bfloat16 l0 = __float2bfloat16(v.x - __bfloat162float(h0));
        __nv_bfloat16 l1 = __float2bfloat16(v.y - __bfloat162float(h1));
        __nv_bfloat16 l2 = __float2bfloat16(v.z - __bfloat162float(h2));
        __nv_bfloat16 l3 = __float2bfloat16(v.w - __bfloat162float(h3));
        long o = (long)m * (KX / 2) + q * 2;
        ((__nv_bfloat162*)hi)[o + 0] = __nv_bfloat162(h0, h1);
        ((__nv_bfloat162*)hi)[o + 1] = __nv_bfloat162(h2, h3);
        ((__nv_bfloat162*)lo)[o + 0] = __nv_bfloat162(l0, l1);
        ((__nv_bfloat162*)lo)[o + 1] = __nv_bfloat162(l2, l3);
    }
}

// ================= HMMA GEMM v2 (hi/lo 3-term): C[M,N] = A[M,K] @ B[N,K]^T + bias =================
// Block tile 128(m) x 256(n), BK=32 halves, 3-stage cp.async pipeline.
// 8 warps as 2(m) x 4(n): warp tile 64x64. Grid: x = m-tiles (fast) for B-tile sharing.
#define LDSW 80                      // padded row stride in bytes (64B data + 16B pad)
#define AH_OFF 0
#define AL_OFF 10240                 // 128*80
#define BH_OFF 20480
#define BL_OFF 40960                 // BH + 256*80
#define STAGE  61440                 // AL+A + 2*B tiles
#define HSMEM  (3 * STAGE)           // 184320 B, 3 stages

__global__ __launch_bounds__(256, 1) void hmma_gemm(
    const __nv_bfloat16* __restrict__ Ah, const __nv_bfloat16* __restrict__ Al,
    const __nv_bfloat16* __restrict__ Bh, const __nv_bfloat16* __restrict__ Bl,
    const float* __restrict__ bias, float* __restrict__ C,
    int K, int Nvalid)
{
    extern __shared__ __align__(128) char smem[];
    uint32_t sb = smem_to_u32(smem);
    int tid = threadIdx.x;
    int lane = tid & 31, wid = tid >> 5;
    int wm = wid & 1, wn = wid >> 1;
    int m0 = blockIdx.x * 128;
    int n0 = blockIdx.y * 256;
    int NK = K >> 5;

    float acc[4][8][4];
#pragma unroll
    for (int a = 0; a < 4; a++)
#pragma unroll
        for (int b = 0; b < 8; b++)
#pragma unroll
            for (int c = 0; c < 4; c++) acc[a][b][c] = 0.0f;

    int lrow = tid >> 2;     // 0..63
    int lq   = tid & 3;

    auto load_stage = [&](int stg) {
        int k0 = stg << 5;
        uint32_t db = sb + (stg % 3) * STAGE;
        // A hi/lo: 128 rows
#pragma unroll
        for (int half = 0; half < 2; half++) {
            int r = half * 64 + lrow;
            uint32_t dst = db + (uint32_t)(r * LDSW + lq * 16);
            long src = (long)(m0 + r) * K + k0 + lq * 8;
            cpasync16(dst + AH_OFF, Ah + src, 16);
            cpasync16(dst + AL_OFF, Al + src, 16);
        }
        // B hi/lo: 256 rows (guard against N overflow)
#pragma unroll
        for (int quad = 0; quad < 4; quad++) {
            int r = quad * 64 + lrow;
            int n = n0 + r;
            uint32_t sz = 16;
            if (n >= Nvalid) { n = 0; sz = 0; }
            uint32_t dst = db + (uint32_t)(r * LDSW + lq * 16);
            long src = (long)n * K + k0 + lq * 8;
            cpasync16(dst + BH_OFF, Bh + src, sz);
            cpasync16(dst + BL_OFF, Bl + src, sz);
        }
    };

    load_stage(0);
    asm volatile("cp.async.commit_group;" ::: "memory");
    load_stage(1);
    asm volatile("cp.async.commit_group;" ::: "memory");

    // fragment index precompute
    int a_row = lane & 15;
    int a_kh  = (lane >> 4) << 3;
    int b_g   = lane >> 3;
    int b_nr  = ((b_g >> 1) << 3) + (lane & 7);
    int b_kh  = (b_g & 1) << 3;

    for (int c = 0; c < NK; c++) {
        if (c + 1 < NK) { asm volatile("cp.async.wait_group 1;" ::: "memory"); }
        else            { asm volatile("cp.async.wait_group 0;" ::: "memory"); }
        __syncthreads();

        if (c + 2 < NK) {
            load_stage(c + 2);
            asm volatile("cp.async.commit_group;" ::: "memory");
        }

        uint32_t aB = sb + (c % 3) * STAGE;
#pragma unroll
        for (int kk = 0; kk < 32; kk += 16) {
            uint32_t bh[16], bl[16], ah[16], al[16];
#pragma unroll
            for (int f2 = 0; f2 < 4; f2++) {
                uint32_t off = (uint32_t)((wn * 64 + f2 * 16 + b_nr) * LDSW + (kk + b_kh) * 2);
                ldm_x4(aB + BH_OFF + off, &bh[f2 * 4]);
                ldm_x4(aB + BL_OFF + off, &bl[f2 * 4]);
            }
#pragma unroll
            for (int fm = 0; fm < 4; fm++) {
                uint32_t off = (uint32_t)((wm * 64 + fm * 16 + a_row) * LDSW + (kk + a_kh) * 2);
                ldm_x4(aB + AH_OFF + off, &ah[fm * 4]);
                ldm_x4(aB + AL_OFF + off, &al[fm * 4]);
            }
#pragma unroll
            for (int fm = 0; fm < 4; fm++)
#pragma unroll
                for (int fn = 0; fn < 8; fn++) {
                    mma16816(acc[fm][fn], &ah[fm * 4], &bh[fn * 2]);
                    mma16816(acc[fm][fn], &ah[fm * 4], &bl[fn * 2]);
                    mma16816(acc[fm][fn], &al[fm * 4], &bh[fn * 2]);
                }
        }
    }

    // epilogue: direct stores + bias (stride V_ odd for logits -> scalar)
    int mbase = m0 + wm * 64 + (lane >> 2);
    int nbase = n0 + wn * 64 + ((lane & 3) << 1);
#pragma unroll
    for (int fm = 0; fm < 4; fm++) {
#pragma unroll
        for (int fn = 0; fn < 8; fn++) {
            int m = mbase + fm * 16;
            int n = nbase + fn * 8;
            float* d = acc[fm][fn];
            if (n < Nvalid) {
                float bv = bias[n];
                C[(long)m * Nvalid + n]       = d[0] + bv;
                C[(long)(m + 8) * Nvalid + n] = d[2] + bv;
            }
            if (n + 1 < Nvalid) {
                float bv = bias[n + 1];
                C[(long)m * Nvalid + n + 1]       = d[1] + bv;
                C[(long)(m + 8) * Nvalid + n + 1] = d[3] + bv;
            }
        }
    }
}

// ================= persistent LSTM recurrence =================
// 128 blocks x 192 threads (6 warps); warp w owns unit u = blk*6 + w.
// Cell state in registers; grid barrier per step; xg operands prefetched one step ahead.
__global__ __launch_bounds__(192) void lstm_persist(
    const float* __restrict__ dh, const float* __restrict__ dctx,
    const float* __restrict__ Whh, const float* __restrict__ bhh,
    float* __restrict__ allh, float* __restrict__ selctx,
    __nv_bfloat16* __restrict__ ahi, __nv_bfloat16* __restrict__ alo)
{
    __shared__ __align__(16) float hs[B_ * H_];
    int tid = threadIdx.x, wid = tid >> 5, lane = tid & 31;
    int u = blockIdx.x * LSTM_WARPS + wid;

    const float4* wp0 = (const float4*)(Whh + (long)(0 * H_ + u) * H_);
    const float4* wp1 = (const float4*)(Whh + (long)(1 * H_ + u) * H_);
    const float4* wp2 = (const float4*)(Whh + (long)(2 * H_ + u) * H_);
    const float4* wp3 = (const float4*)(Whh + (long)(3 * H_ + u) * H_);
    const float4* h4 = (const float4*)hs;

    float creg = 0.0f, b0r = 0.0f, b1r = 0.0f, b2r = 0.0f, b3r = 0.0f;
    float x0 = 0.f, x1 = 0.f, x2 = 0.f, x3 = 0.f;   // current step xg operands
    int lastb = 0;
    if (lane < 16) {
        creg = dctx[lane * H_ + u];
        lastb = g_last[lane];
        b0r = bhh[0 * H_ + u]; b1r = bhh[1 * H_ + u];
        b2r = bhh[2 * H_ + u]; b3r = bhh[3 * H_ + u];
        const float* xr = g_xg + ((long)lane * T_ + 0) * G_;
        x0 = xr[0 * H_ + u]; x1 = xr[1 * H_ + u];
        x2 = xr[2 * H_ + u]; x3 = xr[3 * H_ + u];
    }

    for (int t = 0; t < T_; t++) {
        // prefetch next step's xg operands (independent of everything below)
        float nx0 = 0.f, nx1 = 0.f, nx2 = 0.f, nx3 = 0.f;
        if (lane < 16 && t + 1 < T_) {
            const float* xr = g_xg + ((long)lane * T_ + t + 1) * G_;
            nx0 = __ldcg(xr + 0 * H_ + u); nx1 = __ldcg(xr + 1 * H_ + u);
            nx2 = __ldcg(xr + 2 * H_ + u); nx3 = __ldcg(xr + 3 * H_ + u);
        }

        if (t == 0) {
            for (int i4 = tid; i4 < B_ * H_ / 4; i4 += 192)
                ((float4*)hs)[i4] = __ldcg((const float4*)dh + i4);
        } else {
            for (int i4 = tid; i4 < B_ * H_ / 4; i4 += 192) {
                int b = i4 / (H_ / 4), q = i4 - b * (H_ / 4);
                ((float4*)hs)[i4] = __ldcg((const float4*)(allh + ((long)b * T_ + t - 1) * H_) + q);
            }
        }
        __syncthreads();

        float acc[4][16];
#pragma unroll
        for (int g = 0; g < 4; g++)
#pragma unroll
            for (int b = 0; b < 16; b++) acc[g][b] = 0.0f;

#pragma unroll
        for (int ch = 0; ch < 6; ch++) {
            int k4 = ch * 32 + lane;
            float4 w0 = wp0[k4], w1 = wp1[k4], w2 = wp2[k4], w3 = wp3[k4];
#pragma unroll
            for (int b = 0; b < 16; b++) {
                float4 h = h4[b * 192 + k4];
                acc[0][b] = fmaf(w0.x, h.x, fmaf(w0.y, h.y, fmaf(w0.z, h.z, fmaf(w0.w, h.w, acc[0][b]))));
                acc[1][b] = fmaf(w1.x, h.x, fmaf(w1.y, h.y, fmaf(w1.z, h.z, fmaf(w1.w, h.w, acc[1][b]))));
                acc[2][b] = fmaf(w2.x, h.x, fmaf(w2.y, h.y, fmaf(w2.z, h.z, fmaf(w2.w, h.w, acc[2][b]))));
                acc[3][b] = fmaf(w3.x, h.x, fmaf(w3.y, h.y, fmaf(w3.z, h.z, fmaf(w3.w, h.w, acc[3][b]))));
            }
        }
#pragma unroll
        for (int g = 0; g < 4; g++)
#pragma unroll
            for (int b = 0; b < 16; b++) {
                float v = acc[g][b];
#pragma unroll
                for (int off = 16; off; off >>= 1) v += __shfl_xor_sync(0xffffffffu, v, off);
                acc[g][b] = v;
            }

        if (lane < 16) {
            int b = lane;
            long m = (long)b * T_ + t;
            float xi = acc[0][b] + x0 + b0r;
            float xf = acc[1][b] + x1 + b1r;
            float xg = acc[2][b] + x2 + b2r;
            float xo = acc[3][b] + x3 + b3r;
            float si = 1.0f / (1.0f + expf(-xi));
            float sf = 1.0f / (1.0f + expf(-xf));
            float so = 1.0f / (1.0f + expf(-xo));
            float tg = tanhf(xg);
            creg = sf * creg + si * tg;
            float h = so * tanhf(creg);
            allh[m * H_ + u] = h;
            __nv_bfloat16 hh = __float2bfloat16(h);
            ahi[m * H_ + u] = hh;
            alo[m * H_ + u] = __float2bfloat16(h - __bfloat162float(hh));
            if (t == lastb) selctx[b * H_ + u] = creg;
        }
        x0 = nx0; x1 = nx1; x2 = nx2; x3 = nx3;

        if (t + 1 < T_) {
            __threadfence();
            __syncthreads();
            if (tid == 0) {
                atomicAdd(&g_bar, 1u);
                unsigned tgt = (unsigned)(LSTM_BLOCKS * (t + 1));
                while (ld_acq(&g_bar) < tgt) { }
            }
            __syncthreads();
        }
    }
}

// ================= fused log-softmax =================
__global__ void softmax_k(float* __restrict__ lp) {
    __shared__ float red[256];
    int m = blockIdx.x;
    int tid = threadIdx.x;
    float* row = lp + (long)m * V_;
    float mx = -1e30f;
    for (int j = tid; j < V_; j += 256) mx = fmaxf(mx, row[j]);
    red[tid] = mx; __syncthreads();
    for (int s = 128; s; s >>= 1) { if (tid < s) red[tid] = fmaxf(red[tid], red[tid + s]); __syncthreads(); }
    mx = red[0];
    __syncthreads();
    float sum = 0.0f;
    for (int j = tid; j < V_; j += 256) sum += fexp(row[j] - mx);
    red[tid] = sum; __syncthreads();
    for (int s = 128; s; s >>= 1) { if (tid < s) red[tid] += red[tid + s]; __syncthreads(); }
    float l = mx + logf(red[0]);
    __syncthreads();
    for (int j = tid; j < V_; j += 256) row[j] -= l;
}

// ================= launch =================
extern "C" void kernel_launch(void* const* d_in, const int* in_sizes, int n_in,
                              void* d_out, int out_size)
{
    const int*   ids  = (const int*)d_in[0];
    const int*   mask = (const int*)d_in[1];
    const float* dh   = (const float*)d_in[2];
    const float* dc   = (const float*)d_in[3];
    const float* dapp = (const float*)d_in[4];
    const float* emb  = (const float*)d_in[5];
    const float* Wih  = (const float*)d_in[6];
    const float* Whh  = (const float*)d_in[7];
    const float* bih  = (const float*)d_in[8];
    const float* bhh  = (const float*)d_in[9];
    const float* lmw  = (const float*)d_in[10];
    const float* lmb  = (const float*)d_in[11];
    (void)in_sizes; (void)n_in; (void)out_size;

    float* out    = (float*)d_out;
    float* allh   = out;
    float* selctx = out + (long)MROWS * H_;
    float* lp     = selctx + B_ * H_;

    static int attr_set = 0;
    if (!attr_set) {
        cudaFuncSetAttribute(hmma_gemm, cudaFuncAttributeMaxDynamicSharedMemorySize, HSMEM);
        attr_set = 1;
    }

    __nv_bfloat16 *whi, *wlo, *ahi, *alo, *xah, *xal, *wihh, *wihl;
    float* xg;
    cudaGetSymbolAddress((void**)&whi, g_whi);
    cudaGetSymbolAddress((void**)&wlo, g_wlo);
    cudaGetSymbolAddress((void**)&ahi, g_ahi);
    cudaGetSymbolAddress((void**)&alo, g_alo);
    cudaGetSymbolAddress((void**)&xah, g_xah);
    cudaGetSymbolAddress((void**)&xal, g_xal);
    cudaGetSymbolAddress((void**)&wihh, g_wihh);
    cudaGetSymbolAddress((void**)&wihl, g_wihl);
    cudaGetSymbolAddress((void**)&xg, g_xg);

    setup_k<<<1, 32>>>(mask);

    conv_gather<<<1024, 256>>>(ids, emb, dapp, xah, xal);
    conv_k<<<1024, 256>>>(Wih, wihh, wihl, (long)G_ * KX / 4);

    // xg = [emb||app] @ W_ih^T + b_ih :  grid (m-tiles fast, n-tiles)
    hmma_gemm<<<dim3(MROWS / 128, G_ / 256), 256, HSMEM>>>(
        xah, xal, wihh, wihl, bih, xg, KX, G_);

    conv_k<<<4096, 256>>>(lmw, whi, wlo, (long)V_ * H_ / 4);

    lstm_persist<<<LSTM_BLOCKS, 192>>>(dh, dc, Whh, bhh, allh, selctx, ahi, alo);

    // logits = all_hiddens @ lm_w^T + lm_b
    hmma_gemm<<<dim3(MROWS / 128, (V_ + 255) / 256), 256, HSMEM>>>(
        ahi, alo, whi, wlo, lmb, lp, H_, V_);

    softmax_k<<<MROWS, 256>>>(lp);
}

// round 12
// speedup vs baseline: 2.0022x; 1.0053x over previous
#include <cuda_runtime.h>
#include <cuda_bf16.h>
#include <cstdint>

#define V_  50257
#define H_  768
#define B_  16
#define T_  128
#define G_  3072          // 4*H
#define KX  1536          // 2*H
#define MROWS 2048        // B*T

#define LSTM_BLOCKS 128
#define LSTM_WARPS  6     // units per block; 128*6 = 768 = H_

// ================= scratch (no cudaMalloc allowed) =================
__device__ float g_xg[(long)MROWS * G_];                 // input-side gate projections
__device__ int   g_last[B_];
__device__ unsigned g_bar;                               // grid barrier counter
__device__ __nv_bfloat16 g_whi[(long)V_ * H_];           // lm_w hi
__device__ __nv_bfloat16 g_wlo[(long)V_ * H_];           // lm_w lo
__device__ __nv_bfloat16 g_ahi[(long)MROWS * H_];        // hiddens hi
__device__ __nv_bfloat16 g_alo[(long)MROWS * H_];        // hiddens lo
__device__ __nv_bfloat16 g_xah[(long)MROWS * KX];        // [emb||app] hi
__device__ __nv_bfloat16 g_xal[(long)MROWS * KX];        // [emb||app] lo
__device__ __nv_bfloat16 g_wihh[(long)G_ * KX];          // W_ih hi
__device__ __nv_bfloat16 g_wihl[(long)G_ * KX];          // W_ih lo

// ================= small ptx helpers (baseline PTX only) =================
__device__ __forceinline__ uint32_t smem_to_u32(const void* p) {
    uint32_t a;
    asm("{ .reg .u64 t; cvta.to.shared.u64 t, %1; cvt.u32.u64 %0, t; }" : "=r"(a) : "l"(p));
    return a;
}
__device__ __forceinline__ void cpasync16(uint32_t dst, const void* src, uint32_t sz) {
    asm volatile("cp.async.cg.shared.global [%0], [%1], 16, %2;\n"
        :: "r"(dst), "l"(src), "r"(sz) : "memory");
}
__device__ __forceinline__ void ldm_x4(uint32_t addr, uint32_t* r) {
    asm volatile("ldmatrix.sync.aligned.m8n8.x4.shared.b16 {%0,%1,%2,%3}, [%4];"
        : "=r"(r[0]), "=r"(r[1]), "=r"(r[2]), "=r"(r[3]) : "r"(addr));
}
__device__ __forceinline__ void mma16816(float* d, const uint32_t* a, const uint32_t* b) {
    asm volatile("mma.sync.aligned.m16n8k16.row.col.f32.bf16.bf16.f32 "
        "{%0,%1,%2,%3}, {%4,%5,%6,%7}, {%8,%9}, {%0,%1,%2,%3};"
        : "+f"(d[0]), "+f"(d[1]), "+f"(d[2]), "+f"(d[3])
        : "r"(a[0]), "r"(a[1]), "r"(a[2]), "r"(a[3]), "r"(b[0]), "r"(b[1]));
}
__device__ __forceinline__ unsigned ld_acq(const unsigned* p) {
    unsigned v;
    asm volatile("ld.acquire.gpu.global.u32 %0, [%1];" : "=r"(v) : "l"(p) : "memory");
    return v;
}

// ================= fast exp =================
__device__ __forceinline__ float fexp(float x) {
    x = fmaxf(x, -20.0f);
    float t  = x * 1.4426950408889634f;
    float z  = t + 12582912.0f;
    float nf = z - 12582912.0f;
    float f  = t - nf;
    int   n  = (int)nf;
    float p = fmaf(0.00133335581f, f, 0.00961812911f);
    p = fmaf(p, f, 0.0555041087f);
    p = fmaf(p, f, 0.240226507f);
    p = fmaf(p, f, 0.69314718056f);
    p = fmaf(p, f, 1.0f);
    return p * __int_as_float((n + 127) << 23);
}

// ================= setup =================
__global__ void setup_k(const int* __restrict__ mask) {
    int idx = threadIdx.x;
    if (idx < B_) {
        int s = 0;
        for (int t = 0; t < T_; t++) s += mask[idx * T_ + t];
        g_last[idx] = s - 1;
    }
    if (idx == B_) g_bar = 0u;
}

// ================= hi/lo bf16 conversion =================
__global__ void conv_k(const float* __restrict__ src, __nv_bfloat16* __restrict__ hi,
                       __nv_bfloat16* __restrict__ lo, long n4) {
    long i = (long)blockIdx.x * 256 + threadIdx.x;
    long stride = (long)gridDim.x * 256;
    for (; i < n4; i += stride) {
        float4 v = ((const float4*)src)[i];
        __nv_bfloat16 h0 = __float2bfloat16(v.x), h1 = __float2bfloat16(v.y);
        __nv_bfloat16 h2 = __float2bfloat16(v.z), h3 = __float2bfloat16(v.w);
        __nv_bfloat16 l0 = __float2bfloat16(v.x - __bfloat162float(h0));
        __nv_bfloat16 l1 = __float2bfloat16(v.y - __bfloat162float(h1));
        __nv_bfloat16 l2 = __float2bfloat16(v.z - __bfloat162float(h2));
        __nv_bfloat16 l3 = __float2bfloat16(v.w - __bfloat162float(h3));
        ((__nv_bfloat162*)hi)[i * 2 + 0] = __nv_bfloat162(h0, h1);
        ((__nv_bfloat162*)hi)[i * 2 + 1] = __nv_bfloat162(h2, h3);
        ((__nv_bfloat162*)lo)[i * 2 + 0] = __nv_bfloat162(l0, l1);
        ((__nv_bfloat162*)lo)[i * 2 + 1] = __nv_bfloat162(l2, l3);
    }
}

// build [emb(ids) || append] as hi/lo bf16, rows = MROWS, K = KX
__global__ void conv_gather(const int* __restrict__ ids, const float* __restrict__ emb,
                            const float* __restrict__ app,
                            __nv_bfloat16* __restrict__ hi, __nv_bfloat16* __restrict__ lo) {
    long total = (long)MROWS * (KX / 4);
    long i = (long)blockIdx.x * 256 + threadIdx.x;
    long stride = (long)gridDim.x * 256;
    for (; i < total; i += stride) {
        int m = (int)(i / (KX / 4));
        int q = (int)(i - (long)m * (KX / 4));
        int k = q * 4;
        const float* p;
        if (k < H_) p = emb + (long)ids[m] * H_ + k;
        else        p = app + (long)(m >> 7) * H_ + (k - H_);
        float4 v = *(const float4*)p;
        __nv_bfloat16 h0 = __float2bfloat16(v.x), h1 = __float2bfloat16(v.y);
        __nv_bfloat16 h2 = __float2bfloat16(v.z), h3 = __float2bfloat16(v.w);
        __nv_bfloat16 l0 = __float2bfloat16(v.x - __bfloat162float(h0));
        __nv_bfloat16 l1 = __float2bfloat16(v.y - __bfloat162float(h1));
        __nv_bfloat16 l2 = __float2bfloat16(v.z - __bfloat162float(h2));
        __nv_bfloat16 l3 = __float2bfloat16(v.w - __bfloat162float(h3));
        long o = (long)m * (KX / 2) + q * 2;
        ((__nv_bfloat162*)hi)[o + 0] = __nv_bfloat162(h0, h1);
        ((__nv_bfloat162*)hi)[o + 1] = __nv_bfloat162(h2, h3);
        ((__nv_bfloat162*)lo)[o + 0] = __nv_bfloat162(l0, l1);
        ((__nv_bfloat162*)lo)[o + 1] = __nv_bfloat162(l2, l3);
    }
}

// ================= HMMA GEMM v2 (hi/lo 3-term): C[M,N] = A[M,K] @ B[N,K]^T + bias =================
// Block tile 128(m) x 256(n), BK=32 halves, 3-stage cp.async pipeline.
// 8 warps as 2(m) x 4(n): warp tile 64x64. Grid: x = m-tiles (fast) for B-tile sharing.
#define LDSW 80                      // padded row stride in bytes (64B data + 16B pad)
#define AH_OFF 0
#define AL_OFF 10240                 // 128*80
#define BH_OFF 20480
#define BL_OFF 40960                 // BH + 256*80
#define STAGE  61440                 // AL+A + 2*B tiles
#define HSMEM  (3 * STAGE)           // 184320 B, 3 stages

__global__ __launch_bounds__(256, 1) void hmma_gemm(
    const __nv_bfloat16* __restrict__ Ah, const __nv_bfloat16* __restrict__ Al,
    const __nv_bfloat16* __restrict__ Bh, const __nv_bfloat16* __restrict__ Bl,
    const float* __restrict__ bias, float* __restrict__ C,
    int K, int Nvalid)
{
    extern __shared__ __align__(128) char smem[];
    uint32_t sb = smem_to_u32(smem);
    int tid = threadIdx.x;
    int lane = tid & 31, wid = tid >> 5;
    int wm = wid & 1, wn = wid >> 1;
    int m0 = blockIdx.x * 128;
    int n0 = blockIdx.y * 256;
    int NK = K >> 5;

    float acc[4][8][4];
#pragma unroll
    for (int a = 0; a < 4; a++)
#pragma unroll
        for (int b = 0; b < 8; b++)
#pragma unroll
            for (int c = 0; c < 4; c++) acc[a][b][c] = 0.0f;

    int lrow = tid >> 2;     // 0..63
    int lq   = tid & 3;

    auto load_stage = [&](int stg) {
        int k0 = stg << 5;
        uint32_t db = sb + (stg % 3) * STAGE;
        // A hi/lo: 128 rows
#pragma unroll
        for (int half = 0; half < 2; half++) {
            int r = half * 64 + lrow;
            uint32_t dst = db + (uint32_t)(r * LDSW + lq * 16);
            long src = (long)(m0 + r) * K + k0 + lq * 8;
            cpasync16(dst + AH_OFF, Ah + src, 16);
            cpasync16(dst + AL_OFF, Al + src, 16);
        }
        // B hi/lo: 256 rows (guard against N overflow)
#pragma unroll
        for (int quad = 0; quad < 4; quad++) {
            int r = quad * 64 + lrow;
            int n = n0 + r;
            uint32_t sz = 16;
            if (n >= Nvalid) { n = 0; sz = 0; }
            uint32_t dst = db + (uint32_t)(r * LDSW + lq * 16);
            long src = (long)n * K + k0 + lq * 8;
            cpasync16(dst + BH_OFF, Bh + src, sz);
            cpasync16(dst + BL_OFF, Bl + src, sz);
        }
    };

    load_stage(0);
    asm volatile("cp.async.commit_group;" ::: "memory");
    load_stage(1);
    asm volatile("cp.async.commit_group;" ::: "memory");

    // fragment index precompute
    int a_row = lane & 15;
    int a_kh  = (lane >> 4) << 3;
    int b_g   = lane >> 3;
    int b_nr  = ((b_g >> 1) << 3) + (lane & 7);
    int b_kh  = (b_g & 1) << 3;

    for (int c = 0; c < NK; c++) {
        if (c + 1 < NK) { asm volatile("cp.async.wait_group 1;" ::: "memory"); }
        else            { asm volatile("cp.async.wait_group 0;" ::: "memory"); }
        __syncthreads();

        if (c + 2 < NK) {
            load_stage(c + 2);
            asm volatile("cp.async.commit_group;" ::: "memory");
        }

        uint32_t aB = sb + (c % 3) * STAGE;
#pragma unroll
        for (int kk = 0; kk < 32; kk += 16) {
            uint32_t bh[16], bl[16], ah[16], al[16];
#pragma unroll
            for (int f2 = 0; f2 < 4; f2++) {
                uint32_t off = (uint32_t)((wn * 64 + f2 * 16 + b_nr) * LDSW + (kk + b_kh) * 2);
                ldm_x4(aB + BH_OFF + off, &bh[f2 * 4]);
                ldm_x4(aB + BL_OFF + off, &bl[f2 * 4]);
            }
#pragma unroll
            for (int fm = 0; fm < 4; fm++) {
                uint32_t off = (uint32_t)((wm * 64 + fm * 16 + a_row) * LDSW + (kk + a_kh) * 2);
                ldm_x4(aB + AH_OFF + off, &ah[fm * 4]);
                ldm_x4(aB + AL_OFF + off, &al[fm * 4]);
            }
#pragma unroll
            for (int fm = 0; fm < 4; fm++)
#pragma unroll
                for (int fn = 0; fn < 8; fn++) {
                    mma16816(acc[fm][fn], &ah[fm * 4], &bh[fn * 2]);
                    mma16816(acc[fm][fn], &ah[fm * 4], &bl[fn * 2]);
                    mma16816(acc[fm][fn], &al[fm * 4], &bh[fn * 2]);
                }
        }
    }

    // epilogue: direct stores + bias (stride V_ odd for logits -> scalar)
    int mbase = m0 + wm * 64 + (lane >> 2);
    int nbase = n0 + wn * 64 + ((lane & 3) << 1);
#pragma unroll
    for (int fm = 0; fm < 4; fm++) {
#pragma unroll
        for (int fn = 0; fn < 8; fn++) {
            int m = mbase + fm * 16;
            int n = nbase + fn * 8;
            float* d = acc[fm][fn];
            if (n < Nvalid) {
                float bv = bias[n];
                C[(long)m * Nvalid + n]       = d[0] + bv;
                C[(long)(m + 8) * Nvalid + n] = d[2] + bv;
            }
            if (n + 1 < Nvalid) {
                float bv = bias[n + 1];
                C[(long)m * Nvalid + n + 1]       = d[1] + bv;
                C[(long)(m + 8) * Nvalid + n + 1] = d[3] + bv;
            }
        }
    }
}

// ================= persistent LSTM recurrence =================
// 128 blocks x 192 threads (6 warps); warp w owns unit u = blk*6 + w.
// Cell state in registers; grid barrier per step; xg operands prefetched one step ahead.
__global__ __launch_bounds__(192) void lstm_persist(
    const float* __restrict__ dh, const float* __restrict__ dctx,
    const float* __restrict__ Whh, const float* __restrict__ bhh,
    float* __restrict__ allh, float* __restrict__ selctx,
    __nv_bfloat16* __restrict__ ahi, __nv_bfloat16* __restrict__ alo)
{
    __shared__ __align__(16) float hs[B_ * H_];
    int tid = threadIdx.x, wid = tid >> 5, lane = tid & 31;
    int u = blockIdx.x * LSTM_WARPS + wid;

    const float4* wp0 = (const float4*)(Whh + (long)(0 * H_ + u) * H_);
    const float4* wp1 = (const float4*)(Whh + (long)(1 * H_ + u) * H_);
    const float4* wp2 = (const float4*)(Whh + (long)(2 * H_ + u) * H_);
    const float4* wp3 = (const float4*)(Whh + (long)(3 * H_ + u) * H_);
    const float4* h4 = (const float4*)hs;

    float creg = 0.0f, b0r = 0.0f, b1r = 0.0f, b2r = 0.0f, b3r = 0.0f;
    float x0 = 0.f, x1 = 0.f, x2 = 0.f, x3 = 0.f;   // current step xg operands
    int lastb = 0;
    if (lane < 16) {
        creg = dctx[lane * H_ + u];
        lastb = g_last[lane];
        b0r = bhh[0 * H_ + u]; b1r = bhh[1 * H_ + u];
        b2r = bhh[2 * H_ + u]; b3r = bhh[3 * H_ + u];
        const float* xr = g_xg + ((long)lane * T_ + 0) * G_;
        x0 = xr[0 * H_ + u]; x1 = xr[1 * H_ + u];
        x2 = xr[2 * H_ + u]; x3 = xr[3 * H_ + u];
    }

    for (int t = 0; t < T_; t++) {
        // prefetch next step's xg operands (independent of everything below)
        float nx0 = 0.f, nx1 = 0.f, nx2 = 0.f, nx3 = 0.f;
        if (lane < 16 && t + 1 < T_) {
            const float* xr = g_xg + ((long)lane * T_ + t + 1) * G_;
            nx0 = __ldcg(xr + 0 * H_ + u); nx1 = __ldcg(xr + 1 * H_ + u);
            nx2 = __ldcg(xr + 2 * H_ + u); nx3 = __ldcg(xr + 3 * H_ + u);
        }

        if (t == 0) {
            for (int i4 = tid; i4 < B_ * H_ / 4; i4 += 192)
                ((float4*)hs)[i4] = __ldcg((const float4*)dh + i4);
        } else {
            for (int i4 = tid; i4 < B_ * H_ / 4; i4 += 192) {
                int b = i4 / (H_ / 4), q = i4 - b * (H_ / 4);
                ((float4*)hs)[i4] = __ldcg((const float4*)(allh + ((long)b * T_ + t - 1) * H_) + q);
            }
        }
        __syncthreads();

        float acc[4][16];
#pragma unroll
        for (int g = 0; g < 4; g++)
#pragma unroll
            for (int b = 0; b < 16; b++) acc[g][b] = 0.0f;

#pragma unroll
        for (int ch = 0; ch < 6; ch++) {
            int k4 = ch * 32 + lane;
            float4 w0 = wp0[k4], w1 = wp1[k4], w2 = wp2[k4], w3 = wp3[k4];
#pragma unroll
            for (int b = 0; b < 16; b++) {
                float4 h = h4[b * 192 + k4];
                acc[0][b] = fmaf(w0.x, h.x, fmaf(w0.y, h.y, fmaf(w0.z, h.z, fmaf(w0.w, h.w, acc[0][b]))));
                acc[1][b] = fmaf(w1.x, h.x, fmaf(w1.y, h.y, fmaf(w1.z, h.z, fmaf(w1.w, h.w, acc[1][b]))));
                acc[2][b] = fmaf(w2.x, h.x, fmaf(w2.y, h.y, fmaf(w2.z, h.z, fmaf(w2.w, h.w, acc[2][b]))));
                acc[3][b] = fmaf(w3.x, h.x, fmaf(w3.y, h.y, fmaf(w3.z, h.z, fmaf(w3.w, h.w, acc[3][b]))));
            }
        }
#pragma unroll
        for (int g = 0; g < 4; g++)
#pragma unroll
            for (int b = 0; b < 16; b++) {
                float v = acc[g][b];
#pragma unroll
                for (int off = 16; off; off >>= 1) v += __shfl_xor_sync(0xffffffffu, v, off);
                acc[g][b] = v;
            }

        if (lane < 16) {
            int b = lane;
            long m = (long)b * T_ + t;
            float xi = acc[0][b] + x0 + b0r;
            float xf = acc[1][b] + x1 + b1r;
            float xg = acc[2][b] + x2 + b2r;
            float xo = acc[3][b] + x3 + b3r;
            float si = 1.0f / (1.0f + expf(-xi));
            float sf = 1.0f / (1.0f + expf(-xf));
            float so = 1.0f / (1.0f + expf(-xo));
            float tg = tanhf(xg);
            creg = sf * creg + si * tg;
            float h = so * tanhf(creg);
            allh[m * H_ + u] = h;
            __nv_bfloat16 hh = __float2bfloat16(h);
            ahi[m * H_ + u] = hh;
            alo[m * H_ + u] = __float2bfloat16(h - __bfloat162float(hh));
            if (t == lastb) selctx[b * H_ + u] = creg;
        }
        x0 = nx0; x1 = nx1; x2 = nx2; x3 = nx3;

        if (t + 1 < T_) {
            __threadfence();
            __syncthreads();
            if (tid == 0) {
                atomicAdd(&g_bar, 1u);
                unsigned tgt = (unsigned)(LSTM_BLOCKS * (t + 1));
                while (ld_acq(&g_bar) < tgt) { }
            }
            __syncthreads();
        }
    }
}

// ================= fused log-softmax =================
__global__ void softmax_k(float* __restrict__ lp) {
    __shared__ float red[256];
    int m = blockIdx.x;
    int tid = threadIdx.x;
    float* row = lp + (long)m * V_;
    float mx = -1e30f;
    for (int j = tid; j < V_; j += 256) mx = fmaxf(mx, row[j]);
    red[tid] = mx; __syncthreads();
    for (int s = 128; s; s >>= 1) { if (tid < s) red[tid] = fmaxf(red[tid], red[tid + s]); __syncthreads(); }
    mx = red[0];
    __syncthreads();
    float sum = 0.0f;
    for (int j = tid; j < V_; j += 256) sum += fexp(row[j] - mx);
    red[tid] = sum; __syncthreads();
    for (int s = 128; s; s >>= 1) { if (tid < s) red[tid] += red[tid + s]; __syncthreads(); }
    float l = mx + logf(red[0]);
    __syncthreads();
    for (int j = tid; j < V_; j += 256) row[j] -= l;
}

// ================= launch =================
extern "C" void kernel_launch(void* const* d_in, const int* in_sizes, int n_in,
                              void* d_out, int out_size)
{
    const int*   ids  = (const int*)d_in[0];
    const int*   mask = (const int*)d_in[1];
    const float* dh   = (const float*)d_in[2];
    const float* dc   = (const float*)d_in[3];
    const float* dapp = (const float*)d_in[4];
    const float* emb  = (const float*)d_in[5];
    const float* Wih  = (const float*)d_in[6];
    const float* Whh  = (const float*)d_in[7];
    const float* bih  = (const float*)d_in[8];
    const float* bhh  = (const float*)d_in[9];
    const float* lmw  = (const float*)d_in[10];
    const float* lmb  = (const float*)d_in[11];
    (void)in_sizes; (void)n_in; (void)out_size;

    float* out    = (float*)d_out;
    float* allh   = out;
    float* selctx = out + (long)MROWS * H_;
    float* lp     = selctx + B_ * H_;

    static int attr_set = 0;
    if (!attr_set) {
        cudaFuncSetAttribute(hmma_gemm, cudaFuncAttributeMaxDynamicSharedMemorySize, HSMEM);
        attr_set = 1;
    }

    __nv_bfloat16 *whi, *wlo, *ahi, *alo, *xah, *xal, *wihh, *wihl;
    float* xg;
    cudaGetSymbolAddress((void**)&whi, g_whi);
    cudaGetSymbolAddress((void**)&wlo, g_wlo);
    cudaGetSymbolAddress((void**)&ahi, g_ahi);
    cudaGetSymbolAddress((void**)&alo, g_alo);
    cudaGetSymbolAddress((void**)&xah, g_xah);
    cudaGetSymbolAddress((void**)&xal, g_xal);
    cudaGetSymbolAddress((void**)&wihh, g_wihh);
    cudaGetSymbolAddress((void**)&wihl, g_wihl);
    cudaGetSymbolAddress((void**)&xg, g_xg);

    setup_k<<<1, 32>>>(mask);

    conv_gather<<<1024, 256>>>(ids, emb, dapp, xah, xal);
    conv_k<<<1024, 256>>>(Wih, wihh, wihl, (long)G_ * KX / 4);

    // xg = [emb||app] @ W_ih^T + b_ih :  grid (m-tiles fast, n-tiles)
    hmma_gemm<<<dim3(MROWS / 128, G_ / 256), 256, HSMEM>>>(
        xah, xal, wihh, wihl, bih, xg, KX, G_);

    conv_k<<<4096, 256>>>(lmw, whi, wlo, (long)V_ * H_ / 4);

    lstm_persist<<<LSTM_BLOCKS, 192>>>(dh, dc, Whh, bhh, allh, selctx, ahi, alo);

    // logits = all_hiddens @ lm_w^T + lm_b
    hmma_gemm<<<dim3(MROWS / 128, (V_ + 255) / 256), 256, HSMEM>>>(
        ahi, alo, whi, wlo, lmb, lp, H_, V_);

    softmax_k<<<MROWS, 256>>>(lp);
}

// round 13
// speedup vs baseline: 2.2259x; 1.1118x over previous
#include <cuda_runtime.h>
#include <cuda_bf16.h>
#include <cstdint>

#define V_  50257
#define H_  768
#define B_  16
#define T_  128
#define G_  3072          // 4*H
#define KX  1536          // 2*H
#define MROWS 2048        // B*T

#define LSTM_BLOCKS 128
#define LSTM_WARPS  6     // units per block; 128*6 = 768 = H_

// ================= scratch (no cudaMalloc allowed) =================
__device__ float g_xg[(long)MROWS * G_];                 // input-side gate projections
__device__ int   g_last[B_];
__device__ unsigned g_bar;                               // grid barrier counter
__device__ __nv_bfloat16 g_whi[(long)V_ * H_];           // lm_w hi
__device__ __nv_bfloat16 g_wlo[(long)V_ * H_];           // lm_w lo
__device__ __nv_bfloat16 g_ahi[(long)MROWS * H_];        // hiddens hi (bf16)
__device__ __nv_bfloat16 g_xah[(long)MROWS * KX];        // [emb||app] hi
__device__ __nv_bfloat16 g_xal[(long)MROWS * KX];        // [emb||app] lo
__device__ __nv_bfloat16 g_wihh[(long)G_ * KX];          // W_ih hi
__device__ __nv_bfloat16 g_wihl[(long)G_ * KX];          // W_ih lo

// ================= small ptx helpers (baseline PTX only) =================
__device__ __forceinline__ uint32_t smem_to_u32(const void* p) {
    uint32_t a;
    asm("{ .reg .u64 t; cvta.to.shared.u64 t, %1; cvt.u32.u64 %0, t; }" : "=r"(a) : "l"(p));
    return a;
}
__device__ __forceinline__ void cpasync16(uint32_t dst, const void* src, uint32_t sz) {
    asm volatile("cp.async.cg.shared.global [%0], [%1], 16, %2;\n"
        :: "r"(dst), "l"(src), "r"(sz) : "memory");
}
__device__ __forceinline__ void ldm_x4(uint32_t addr, uint32_t* r) {
    asm volatile("ldmatrix.sync.aligned.m8n8.x4.shared.b16 {%0,%1,%2,%3}, [%4];"
        : "=r"(r[0]), "=r"(r[1]), "=r"(r[2]), "=r"(r[3]) : "r"(addr));
}
__device__ __forceinline__ void mma16816(float* d, const uint32_t* a, const uint32_t* b) {
    asm volatile("mma.sync.aligned.m16n8k16.row.col.f32.bf16.bf16.f32 "
        "{%0,%1,%2,%3}, {%4,%5,%6,%7}, {%8,%9}, {%0,%1,%2,%3};"
        : "+f"(d[0]), "+f"(d[1]), "+f"(d[2]), "+f"(d[3])
        : "r"(a[0]), "r"(a[1]), "r"(a[2]), "r"(a[3]), "r"(b[0]), "r"(b[1]));
}
__device__ __forceinline__ unsigned ld_acq(const unsigned* p) {
    unsigned v;
    asm volatile("ld.acquire.gpu.global.u32 %0, [%1];" : "=r"(v) : "l"(p) : "memory");
    return v;
}

// ================= fast exp =================
__device__ __forceinline__ float fexp(float x) {
    x = fmaxf(x, -20.0f);
    float t  = x * 1.4426950408889634f;
    float z  = t + 12582912.0f;
    float nf = z - 12582912.0f;
    float f  = t - nf;
    int   n  = (int)nf;
    float p = fmaf(0.00133335581f, f, 0.00961812911f);
    p = fmaf(p, f, 0.0555041087f);
    p = fmaf(p, f, 0.240226507f);
    p = fmaf(p, f, 0.69314718056f);
    p = fmaf(p, f, 1.0f);
    return p * __int_as_float((n + 127) << 23);
}

// ================= setup =================
__global__ void setup_k(const int* __restrict__ mask) {
    int idx = threadIdx.x;
    if (idx < B_) {
        int s = 0;
        for (int t = 0; t < T_; t++) s += mask[idx * T_ + t];
        g_last[idx] = s - 1;
    }
    if (idx == B_) g_bar = 0u;
}

// ================= hi/lo bf16 conversion =================
__global__ void conv_k(const float* __restrict__ src, __nv_bfloat16* __restrict__ hi,
                       __nv_bfloat16* __restrict__ lo, long n4) {
    long i = (long)blockIdx.x * 256 + threadIdx.x;
    long stride = (long)gridDim.x * 256;
    for (; i < n4; i += stride) {
        float4 v = ((const float4*)src)[i];
        __nv_bfloat16 h0 = __float2bfloat16(v.x), h1 = __float2bfloat16(v.y);
        __nv_bfloat16 h2 = __float2bfloat16(v.z), h3 = __float2bfloat16(v.w);
        __nv_bfloat16 l0 = __float2bfloat16(v.x - __bfloat162float(h0));
        __nv_bfloat16 l1 = __float2bfloat16(v.y - __bfloat162float(h1));
        __nv_bfloat16 l2 = __float2bfloat16(v.z - __bfloat162float(h2));
        __nv_bfloat16 l3 = __float2bfloat16(v.w - __bfloat162float(h3));
        ((__nv_bfloat162*)hi)[i * 2 + 0] = __nv_bfloat162(h0, h1);
        ((__nv_bfloat162*)hi)[i * 2 + 1] = __nv_bfloat162(h2, h3);
        ((__nv_bfloat162*)lo)[i * 2 + 0] = __nv_bfloat162(l0, l1);
        ((__nv_bfloat162*)lo)[i * 2 + 1] = __nv_bfloat162(l2, l3);
    }
}

// build [emb(ids) || append] as hi/lo bf16, rows = MROWS, K = KX
__global__ void conv_gather(const int* __restrict__ ids, const float* __restrict__ emb,
                            const float* __restrict__ app,
                            __nv_bfloat16* __restrict__ hi, __nv_bfloat16* __restrict__ lo) {
    long total = (long)MROWS * (KX / 4);
    long i = (long)blockIdx.x * 256 + threadIdx.x;
    long stride = (long)gridDim.x * 256;
    for (; i < total; i += stride) {
        int m = (int)(i / (KX / 4));
        int q = (int)(i - (long)m * (KX / 4));
        int k = q * 4;
        const float* p;
        if (k < H_) p = emb + (long)ids[m] * H_ + k;
        else        p = app + (long)(m >> 7) * H_ + (k - H_);
        float4 v = *(const float4*)p;
        __nv_bfloat16 h0 = __float2bfloat16(v.x), h1 = __float2bfloat16(v.y);
        __nv_bfloat16 h2 = __float2bfloat16(v.z), h3 = __float2bfloat16(v.w);
        __nv_bfloat16 l0 = __float2bfloat16(v.x - __bfloat162float(h0));
        __nv_bfloat16 l1 = __float2bfloat16(v.y - __bfloat162float(h1));
        __nv_bfloat16 l2 = __float2bfloat16(v.z - __bfloat162float(h2));
        __nv_bfloat16 l3 = __float2bfloat16(v.w - __bfloat162float(h3));
        long o = (long)m * (KX / 2) + q * 2;
        ((__nv_bfloat162*)hi)[o + 0] = __nv_bfloat162(h0, h1);
        ((__nv_bfloat162*)hi)[o + 1] = __nv_bfloat162(h2, h3);
        ((__nv_bfloat162*)lo)[o + 0] = __nv_bfloat162(l0, l1);
        ((__nv_bfloat162*)lo)[o + 1] = __nv_bfloat162(l2, l3);
    }
}

// ================= HMMA GEMM v3 (templated 2/3-term): C = A @ B^T + bias =================
// Block 128x128, warp tile 64x32 (8 warps 2m x 4n), BK=32, 4-stage cp.async pipeline,
// ONE __syncthreads per K-chunk. NTERMS=3: AhBh+AhBl+AlBh; NTERMS=2: AhBh+AhBl.
#define LDSW  80                     // padded row stride bytes (64B data + 16B pad)
#define TILEB (128 * LDSW)           // 10240 B per 128-row tile
// stage layout: Ah @0, Bh @TILEB, Bl @2*TILEB, [Al @3*TILEB]
#define NSTAGES 4

template<int NTERMS>
__global__ __launch_bounds__(256, 1) void hmma_gemm(
    const __nv_bfloat16* __restrict__ Ah, const __nv_bfloat16* __restrict__ Al,
    const __nv_bfloat16* __restrict__ Bh, const __nv_bfloat16* __restrict__ Bl,
    const float* __restrict__ bias, float* __restrict__ C,
    int K, int Nvalid)
{
    constexpr int NMAT  = (NTERMS == 3) ? 4 : 3;
    constexpr int STAGE = NMAT * TILEB;

    extern __shared__ __align__(128) char smem[];
    uint32_t sb = smem_to_u32(smem);
    int tid = threadIdx.x;
    int lane = tid & 31, wid = tid >> 5;
    int wm = wid & 1, wn = wid >> 1;
    int m0 = blockIdx.x * 128;          // m-fast for B-tile L2 reuse
    int n0 = blockIdx.y * 128;
    int NK = K >> 5;

    float acc[4][4][4];
#pragma unroll
    for (int a = 0; a < 4; a++)
#pragma unroll
        for (int b = 0; b < 4; b++)
#pragma unroll
            for (int c = 0; c < 4; c++) acc[a][b][c] = 0.0f;

    int lrow = tid >> 2;     // 0..63
    int lq   = tid & 3;

    auto load_stage = [&](int stg) {
        int k0 = stg << 5;
        uint32_t db = sb + (stg & (NSTAGES - 1)) * STAGE;
#pragma unroll
        for (int half = 0; half < 2; half++) {
            int r = half * 64 + lrow;
            uint32_t dof = (uint32_t)(r * LDSW + lq * 16);
            long asrc = (long)(m0 + r) * K + k0 + lq * 8;
            cpasync16(db + dof, Ah + asrc, 16);
            if (NTERMS == 3) cpasync16(db + 3 * TILEB + dof, Al + asrc, 16);
            int n = n0 + r;
            uint32_t sz = 16;
            if (n >= Nvalid) { n = 0; sz = 0; }
            long bsrc = (long)n * K + k0 + lq * 8;
            cpasync16(db + TILEB + dof, Bh + bsrc, sz);
            cpasync16(db + 2 * TILEB + dof, Bl + bsrc, sz);
        }
    };

    // prologue: fill NSTAGES-1 stages
#pragma unroll
    for (int s = 0; s < NSTAGES - 1; s++) {
        if (s < NK) load_stage(s);
        asm volatile("cp.async.commit_group;" ::: "memory");
    }

    int a_row = lane & 15;
    int a_kh  = (lane >> 4) << 3;
    int b_g   = lane >> 3;
    int b_nr  = ((b_g >> 1) << 3) + (lane & 7);
    int b_kh  = (b_g & 1) << 3;

    for (int c = 0; c < NK; c++) {
        asm volatile("cp.async.wait_group %0;" :: "n"(NSTAGES - 2) : "memory");
        __syncthreads();

        // refill stage c+NSTAGES-1 (buffer last read in chunk c-1; safe after sync)
        if (c + NSTAGES - 1 < NK) load_stage(c + NSTAGES - 1);
        asm volatile("cp.async.commit_group;" ::: "memory");

        uint32_t aB = sb + (c & (NSTAGES - 1)) * STAGE;
#pragma unroll
        for (int kk = 0; kk < 32; kk += 16) {
            uint32_t bh[8], bl[8], ah[16], al[16];
#pragma unroll
            for (int f2 = 0; f2 < 2; f2++) {
                uint32_t off = (uint32_t)((wn * 32 + f2 * 16 + b_nr) * LDSW + (kk + b_kh) * 2);
                ldm_x4(aB + TILEB + off, &bh[f2 * 4]);
                ldm_x4(aB + 2 * TILEB + off, &bl[f2 * 4]);
            }
#pragma unroll
            for (int fm = 0; fm < 4; fm++) {
                uint32_t off = (uint32_t)((wm * 64 + fm * 16 + a_row) * LDSW + (kk + a_kh) * 2);
                ldm_x4(aB + off, &ah[fm * 4]);
                if (NTERMS == 3) ldm_x4(aB + 3 * TILEB + off, &al[fm * 4]);
            }
#pragma unroll
            for (int fm = 0; fm < 4; fm++)
#pragma unroll
                for (int fn = 0; fn < 4; fn++) {
                    mma16816(acc[fm][fn], &ah[fm * 4], &bh[fn * 2]);
                    mma16816(acc[fm][fn], &ah[fm * 4], &bl[fn * 2]);
                    if (NTERMS == 3) mma16816(acc[fm][fn], &al[fm * 4], &bh[fn * 2]);
                }
        }
    }

    // epilogue: direct stores + bias
    int mbase = m0 + wm * 64 + (lane >> 2);
    int nbase = n0 + wn * 32 + ((lane & 3) << 1);
#pragma unroll
    for (int fm = 0; fm < 4; fm++) {
#pragma unroll
        for (int fn = 0; fn < 4; fn++) {
            int m = mbase + fm * 16;
            int n = nbase + fn * 8;
            float* d = acc[fm][fn];
            if (n < Nvalid) {
                float bv = bias[n];
                C[(long)m * Nvalid + n]       = d[0] + bv;
                C[(long)(m + 8) * Nvalid + n] = d[2] + bv;
            }
            if (n + 1 < Nvalid) {
                float bv = bias[n + 1];
                C[(long)m * Nvalid + n + 1]       = d[1] + bv;
                C[(long)(m + 8) * Nvalid + n + 1] = d[3] + bv;
            }
        }
    }
}

// ================= persistent LSTM recurrence =================
__global__ __launch_bounds__(192) void lstm_persist(
    const float* __restrict__ dh, const float* __restrict__ dctx,
    const float* __restrict__ Whh, const float* __restrict__ bhh,
    float* __restrict__ allh, float* __restrict__ selctx,
    __nv_bfloat16* __restrict__ ahi)
{
    __shared__ __align__(16) float hs[B_ * H_];
    int tid = threadIdx.x, wid = tid >> 5, lane = tid & 31;
    int u = blockIdx.x * LSTM_WARPS + wid;

    const float4* wp0 = (const float4*)(Whh + (long)(0 * H_ + u) * H_);
    const float4* wp1 = (const float4*)(Whh + (long)(1 * H_ + u) * H_);
    const float4* wp2 = (const float4*)(Whh + (long)(2 * H_ + u) * H_);
    const float4* wp3 = (const float4*)(Whh + (long)(3 * H_ + u) * H_);
    const float4* h4 = (const float4*)hs;

    float creg = 0.0f, b0r = 0.0f, b1r = 0.0f, b2r = 0.0f, b3r = 0.0f;
    float x0 = 0.f, x1 = 0.f, x2 = 0.f, x3 = 0.f;
    int lastb = 0;
    if (lane < 16) {
        creg = dctx[lane * H_ + u];
        lastb = g_last[lane];
        b0r = bhh[0 * H_ + u]; b1r = bhh[1 * H_ + u];
        b2r = bhh[2 * H_ + u]; b3r = bhh[3 * H_ + u];
        const float* xr = g_xg + ((long)lane * T_ + 0) * G_;
        x0 = xr[0 * H_ + u]; x1 = xr[1 * H_ + u];
        x2 = xr[2 * H_ + u]; x3 = xr[3 * H_ + u];
    }

    for (int t = 0; t < T_; t++) {
        float nx0 = 0.f, nx1 = 0.f, nx2 = 0.f, nx3 = 0.f;
        if (lane < 16 && t + 1 < T_) {
            const float* xr = g_xg + ((long)lane * T_ + t + 1) * G_;
            nx0 = __ldcg(xr + 0 * H_ + u); nx1 = __ldcg(xr + 1 * H_ + u);
            nx2 = __ldcg(xr + 2 * H_ + u); nx3 = __ldcg(xr + 3 * H_ + u);
        }

        if (t == 0) {
            for (int i4 = tid; i4 < B_ * H_ / 4; i4 += 192)
                ((float4*)hs)[i4] = __ldcg((const float4*)dh + i4);
        } else {
            for (int i4 = tid; i4 < B_ * H_ / 4; i4 += 192) {
                int b = i4 / (H_ / 4), q = i4 - b * (H_ / 4);
                ((float4*)hs)[i4] = __ldcg((const float4*)(allh + ((long)b * T_ + t - 1) * H_) + q);
            }
        }
        __syncthreads();

        float acc[4][16];
#pragma unroll
        for (int g = 0; g < 4; g++)
#pragma unroll
            for (int b = 0; b < 16; b++) acc[g][b] = 0.0f;

#pragma unroll
        for (int ch = 0; ch < 6; ch++) {
            int k4 = ch * 32 + lane;
            float4 w0 = wp0[k4], w1 = wp1[k4], w2 = wp2[k4], w3 = wp3[k4];
#pragma unroll
            for (int b = 0; b < 16; b++) {
                float4 h = h4[b * 192 + k4];
                acc[0][b] = fmaf(w0.x, h.x, fmaf(w0.y, h.y, fmaf(w0.z, h.z, fmaf(w0.w, h.w, acc[0][b]))));
                acc[1][b] = fmaf(w1.x, h.x, fmaf(w1.y, h.y, fmaf(w1.z, h.z, fmaf(w1.w, h.w, acc[1][b]))));
                acc[2][b] = fmaf(w2.x, h.x, fmaf(w2.y, h.y, fmaf(w2.z, h.z, fmaf(w2.w, h.w, acc[2][b]))));
                acc[3][b] = fmaf(w3.x, h.x, fmaf(w3.y, h.y, fmaf(w3.z, h.z, fmaf(w3.w, h.w, acc[3][b]))));
            }
        }
#pragma unroll
        for (int g = 0; g < 4; g++)
#pragma unroll
            for (int b = 0; b < 16; b++) {
                float v = acc[g][b];
#pragma unroll
                for (int off = 16; off; off >>= 1) v += __shfl_xor_sync(0xffffffffu, v, off);
                acc[g][b] = v;
            }

        if (lane < 16) {
            int b = lane;
            long m = (long)b * T_ + t;
            float xi = acc[0][b] + x0 + b0r;
            float xf = acc[1][b] + x1 + b1r;
            float xg = acc[2][b] + x2 + b2r;
            float xo = acc[3][b] + x3 + b3r;
            float si = 1.0f / (1.0f + expf(-xi));
            float sf = 1.0f / (1.0f + expf(-xf));
            float so = 1.0f / (1.0f + expf(-xo));
            float tg = tanhf(xg);
            creg = sf * creg + si * tg;
            float h = so * tanhf(creg);
            allh[m * H_ + u] = h;
            ahi[m * H_ + u] = __float2bfloat16(h);
            if (t == lastb) selctx[b * H_ + u] = creg;
        }
        x0 = nx0; x1 = nx1; x2 = nx2; x3 = nx3;

        if (t + 1 < T_) {
            __threadfence();
            __syncthreads();
            if (tid == 0) {
                atomicAdd(&g_bar, 1u);
                unsigned tgt = (unsigned)(LSTM_BLOCKS * (t + 1));
                while (ld_acq(&g_bar) < tgt) { }
            }
            __syncthreads();
        }
    }
}

// ================= fused log-softmax =================
__global__ void softmax_k(float* __restrict__ lp) {
    __shared__ float red[256];
    int m = blockIdx.x;
    int tid = threadIdx.x;
    float* row = lp + (long)m * V_;
    float mx = -1e30f;
    for (int j = tid; j < V_; j += 256) mx = fmaxf(mx, row[j]);
    red[tid] = mx; __syncthreads();
    for (int s = 128; s; s >>= 1) { if (tid < s) red[tid] = fmaxf(red[tid], red[tid + s]); __syncthreads(); }
    mx = red[0];
    __syncthreads();
    float sum = 0.0f;
    for (int j = tid; j < V_; j += 256) sum += fexp(row[j] - mx);
    red[tid] = sum; __syncthreads();
    for (int s = 128; s; s >>= 1) { if (tid < s) red[tid] += red[tid + s]; __syncthreads(); }
    float l = mx + logf(red[0]);
    __syncthreads();
    for (int j = tid; j < V_; j += 256) row[j] -= l;
}

// ================= launch =================
extern "C" void kernel_launch(void* const* d_in, const int* in_sizes, int n_in,
                              void* d_out, int out_size)
{
    const int*   ids  = (const int*)d_in[0];
    const int*   mask = (const int*)d_in[1];
    const float* dh   = (const float*)d_in[2];
    const float* dc   = (const float*)d_in[3];
    const float* dapp = (const float*)d_in[4];
    const float* emb  = (const float*)d_in[5];
    const float* Wih  = (const float*)d_in[6];
    const float* Whh  = (const float*)d_in[7];
    const float* bih  = (const float*)d_in[8];
    const float* bhh  = (const float*)d_in[9];
    const float* lmw  = (const float*)d_in[10];
    const float* lmb  = (const float*)d_in[11];
    (void)in_sizes; (void)n_in; (void)out_size;

    float* out    = (float*)d_out;
    float* allh   = out;
    float* selctx = out + (long)MROWS * H_;
    float* lp     = selctx + B_ * H_;

    constexpr int SMEM3 = NSTAGES * 4 * TILEB;   // 163840
    constexpr int SMEM2 = NSTAGES * 3 * TILEB;   // 122880

    static int attr_set = 0;
    if (!attr_set) {
        cudaFuncSetAttribute(hmma_gemm<3>, cudaFuncAttributeMaxDynamicSharedMemorySize, SMEM3);
        cudaFuncSetAttribute(hmma_gemm<2>, cudaFuncAttributeMaxDynamicSharedMemorySize, SMEM2);
        attr_set = 1;
    }

    __nv_bfloat16 *whi, *wlo, *ahi, *xah, *xal, *wihh, *wihl;
    float* xg;
    cudaGetSymbolAddress((void**)&whi, g_whi);
    cudaGetSymbolAddress((void**)&wlo, g_wlo);
    cudaGetSymbolAddress((void**)&ahi, g_ahi);
    cudaGetSymbolAddress((void**)&xah, g_xah);
    cudaGetSymbolAddress((void**)&xal, g_xal);
    cudaGetSymbolAddress((void**)&wihh, g_wihh);
    cudaGetSymbolAddress((void**)&wihl, g_wihl);
    cudaGetSymbolAddress((void**)&xg, g_xg);

    setup_k<<<1, 32>>>(mask);

    conv_gather<<<1024, 256>>>(ids, emb, dapp, xah, xal);
    conv_k<<<1024, 256>>>(Wih, wihh, wihl, (long)G_ * KX / 4);

    // xg = [emb||app] @ W_ih^T + b_ih  (3-term: feeds recurrence, keep accuracy)
    hmma_gemm<3><<<dim3(MROWS / 128, G_ / 128), 256, SMEM3>>>(
        xah, xal, wihh, wihl, bih, xg, KX, G_);

    conv_k<<<4096, 256>>>(lmw, whi, wlo, (long)V_ * H_ / 4);

    lstm_persist<<<LSTM_BLOCKS, 192>>>(dh, dc, Whh, bhh, allh, selctx, ahi);

    // logits = hiddens(bf16 hi) @ lm_w(hi+lo)^T + lm_b  (2-term; Al unused)
    hmma_gemm<2><<<dim3(MROWS / 128, (V_ + 127) / 128), 256, SMEM2>>>(
        ahi, ahi, whi, wlo, lmb, lp, H_, V_);

    softmax_k<<<MROWS, 256>>>(lp);
}

// round 14
// speedup vs baseline: 2.4398x; 1.0961x over previous
#include <cuda_runtime.h>
#include <cuda_bf16.h>
#include <cstdint>

#define V_  50257
#define H_  768
#define B_  16
#define T_  128
#define G_  3072          // 4*H
#define KX  1536          // 2*H
#define MROWS 2048        // B*T

#define LSTM_BLOCKS 128
#define LSTM_WARPS  6     // units per block; 128*6 = 768 = H_

// ================= scratch (no cudaMalloc allowed) =================
__device__ float g_xg[(long)MROWS * G_];                 // input-side gate projections
__device__ int   g_last[B_];
__device__ unsigned g_bar;                               // grid barrier counter
__device__ __nv_bfloat16 g_whi[(long)V_ * H_];           // lm_w hi
__device__ __nv_bfloat16 g_wlo[(long)V_ * H_];           // lm_w lo
__device__ __nv_bfloat16 g_ahi[(long)MROWS * H_];        // hiddens hi (bf16)
__device__ __nv_bfloat16 g_xah[(long)MROWS * KX];        // [emb||app] hi
__device__ __nv_bfloat16 g_xal[(long)MROWS * KX];        // [emb||app] lo
__device__ __nv_bfloat16 g_wihh[(long)G_ * KX];          // W_ih hi
__device__ __nv_bfloat16 g_wihl[(long)G_ * KX];          // W_ih lo

// ================= small ptx helpers (baseline PTX only) =================
__device__ __forceinline__ uint32_t smem_to_u32(const void* p) {
    uint32_t a;
    asm("{ .reg .u64 t; cvta.to.shared.u64 t, %1; cvt.u32.u64 %0, t; }" : "=r"(a) : "l"(p));
    return a;
}
__device__ __forceinline__ void cpasync16(uint32_t dst, const void* src, uint32_t sz) {
    asm volatile("cp.async.cg.shared.global [%0], [%1], 16, %2;\n"
        :: "r"(dst), "l"(src), "r"(sz) : "memory");
}
__device__ __forceinline__ void ldm_x4(uint32_t addr, uint32_t* r) {
    asm volatile("ldmatrix.sync.aligned.m8n8.x4.shared.b16 {%0,%1,%2,%3}, [%4];"
        : "=r"(r[0]), "=r"(r[1]), "=r"(r[2]), "=r"(r[3]) : "r"(addr));
}
__device__ __forceinline__ void mma16816(float* d, const uint32_t* a, const uint32_t* b) {
    asm volatile("mma.sync.aligned.m16n8k16.row.col.f32.bf16.bf16.f32 "
        "{%0,%1,%2,%3}, {%4,%5,%6,%7}, {%8,%9}, {%0,%1,%2,%3};"
        : "+f"(d[0]), "+f"(d[1]), "+f"(d[2]), "+f"(d[3])
        : "r"(a[0]), "r"(a[1]), "r"(a[2]), "r"(a[3]), "r"(b[0]), "r"(b[1]));
}
__device__ __forceinline__ unsigned ld_acq(const unsigned* p) {
    unsigned v;
    asm volatile("ld.acquire.gpu.global.u32 %0, [%1];" : "=r"(v) : "l"(p) : "memory");
    return v;
}
__device__ __forceinline__ void red_release_add(unsigned* p, unsigned v) {
    asm volatile("red.release.gpu.global.add.u32 [%0], %1;" :: "l"(p), "r"(v) : "memory");
}

// ================= fast exp =================
__device__ __forceinline__ float fexp(float x) {
    x = fmaxf(x, -20.0f);
    float t  = x * 1.4426950408889634f;
    float z  = t + 12582912.0f;
    float nf = z - 12582912.0f;
    float f  = t - nf;
    int   n  = (int)nf;
    float p = fmaf(0.00133335581f, f, 0.00961812911f);
    p = fmaf(p, f, 0.0555041087f);
    p = fmaf(p, f, 0.240226507f);
    p = fmaf(p, f, 0.69314718056f);
    p = fmaf(p, f, 1.0f);
    return p * __int_as_float((n + 127) << 23);
}

// ================= setup =================
__global__ void setup_k(const int* __restrict__ mask) {
    int idx = threadIdx.x;
    if (idx < B_) {
        int s = 0;
        for (int t = 0; t < T_; t++) s += mask[idx * T_ + t];
        g_last[idx] = s - 1;
    }
    if (idx == B_) g_bar = 0u;
}

// ================= hi/lo bf16 conversion =================
__global__ void conv_k(const float* __restrict__ src, __nv_bfloat16* __restrict__ hi,
                       __nv_bfloat16* __restrict__ lo, long n4) {
    long i = (long)blockIdx.x * 256 + threadIdx.x;
    long stride = (long)gridDim.x * 256;
    for (; i < n4; i += stride) {
        float4 v = ((const float4*)src)[i];
        __nv_bfloat16 h0 = __float2bfloat16(v.x), h1 = __float2bfloat16(v.y);
        __nv_bfloat16 h2 = __float2bfloat16(v.z), h3 = __float2bfloat16(v.w);
        __nv_bfloat16 l0 = __float2bfloat16(v.x - __bfloat162float(h0));
        __nv_bfloat16 l1 = __float2bfloat16(v.y - __bfloat162float(h1));
        __nv_bfloat16 l2 = __float2bfloat16(v.z - __bfloat162float(h2));
        __nv_bfloat16 l3 = __float2bfloat16(v.w - __bfloat162float(h3));
        ((__nv_bfloat162*)hi)[i * 2 + 0] = __nv_bfloat162(h0, h1);
        ((__nv_bfloat162*)hi)[i * 2 + 1] = __nv_bfloat162(h2, h3);
        ((__nv_bfloat162*)lo)[i * 2 + 0] = __nv_bfloat162(l0, l1);
        ((__nv_bfloat162*)lo)[i * 2 + 1] = __nv_bfloat162(l2, l3);
    }
}

// build [emb(ids) || append] as hi/lo bf16, rows = MROWS, K = KX
__global__ void conv_gather(const int* __restrict__ ids, const float* __restrict__ emb,
                            const float* __restrict__ app,
                            __nv_bfloat16* __restrict__ hi, __nv_bfloat16* __restrict__ lo) {
    long total = (long)MROWS * (KX / 4);
    long i = (long)blockIdx.x * 256 + threadIdx.x;
    long stride = (long)gridDim.x * 256;
    for (; i < total; i += stride) {
        int m = (int)(i / (KX / 4));
        int q = (int)(i - (long)m * (KX / 4));
        int k = q * 4;
        const float* p;
        if (k < H_) p = emb + (long)ids[m] * H_ + k;
        else        p = app + (long)(m >> 7) * H_ + (k - H_);
        float4 v = *(const float4*)p;
        __nv_bfloat16 h0 = __float2bfloat16(v.x), h1 = __float2bfloat16(v.y);
        __nv_bfloat16 h2 = __float2bfloat16(v.z), h3 = __float2bfloat16(v.w);
        __nv_bfloat16 l0 = __float2bfloat16(v.x - __bfloat162float(h0));
        __nv_bfloat16 l1 = __float2bfloat16(v.y - __bfloat162float(h1));
        __nv_bfloat16 l2 = __float2bfloat16(v.z - __bfloat162float(h2));
        __nv_bfloat16 l3 = __float2bfloat16(v.w - __bfloat162float(h3));
        long o = (long)m * (KX / 2) + q * 2;
        ((__nv_bfloat162*)hi)[o + 0] = __nv_bfloat162(h0, h1);
        ((__nv_bfloat162*)hi)[o + 1] = __nv_bfloat162(h2, h3);
        ((__nv_bfloat162*)lo)[o + 0] = __nv_bfloat162(l0, l1);
        ((__nv_bfloat162*)lo)[o + 1] = __nv_bfloat162(l2, l3);
    }
}

// ================= HMMA GEMM (templated terms/stages): C = A @ B^T + bias =================
// Block 128x128, warp tile 64x32 (8 warps 2m x 4n), BK=32, NST-stage cp.async pipeline,
// ONE __syncthreads per K-chunk. NTERMS=3: AhBh+AhBl+AlBh; NTERMS=2: AhBh+AhBl.
// NTERMS=2 uses 3 stages (92KB smem) -> 2 CTAs/SM for latency hiding.
#define LDSW  80                     // padded row stride bytes (64B data + 16B pad)
#define TILEB (128 * LDSW)           // 10240 B per 128-row tile

template<int NTERMS, int NST>
__global__ __launch_bounds__(256, (NTERMS == 2 ? 2 : 1)) void hmma_gemm(
    const __nv_bfloat16* __restrict__ Ah, const __nv_bfloat16* __restrict__ Al,
    const __nv_bfloat16* __restrict__ Bh, const __nv_bfloat16* __restrict__ Bl,
    const float* __restrict__ bias, float* __restrict__ C,
    int K, int Nvalid)
{
    constexpr int NMAT  = (NTERMS == 3) ? 4 : 3;
    constexpr int STAGE = NMAT * TILEB;

    extern __shared__ __align__(128) char smem[];
    uint32_t sb = smem_to_u32(smem);
    int tid = threadIdx.x;
    int lane = tid & 31, wid = tid >> 5;
    int wm = wid & 1, wn = wid >> 1;
    int m0 = blockIdx.x * 128;          // m-fast for B-tile L2 reuse
    int n0 = blockIdx.y * 128;
    int NK = K >> 5;

    float acc[4][4][4];
#pragma unroll
    for (int a = 0; a < 4; a++)
#pragma unroll
        for (int b = 0; b < 4; b++)
#pragma unroll
            for (int c = 0; c < 4; c++) acc[a][b][c] = 0.0f;

    int lrow = tid >> 2;     // 0..63
    int lq   = tid & 3;

    auto load_stage = [&](int stg) {
        int k0 = stg << 5;
        uint32_t db = sb + (stg % NST) * STAGE;
#pragma unroll
        for (int half = 0; half < 2; half++) {
            int r = half * 64 + lrow;
            uint32_t dof = (uint32_t)(r * LDSW + lq * 16);
            long asrc = (long)(m0 + r) * K + k0 + lq * 8;
            cpasync16(db + dof, Ah + asrc, 16);
            if (NTERMS == 3) cpasync16(db + 3 * TILEB + dof, Al + asrc, 16);
            int n = n0 + r;
            uint32_t sz = 16;
            if (n >= Nvalid) { n = 0; sz = 0; }
            long bsrc = (long)n * K + k0 + lq * 8;
            cpasync16(db + TILEB + dof, Bh + bsrc, sz);
            cpasync16(db + 2 * TILEB + dof, Bl + bsrc, sz);
        }
    };

    // prologue: fill NST-1 stages
#pragma unroll
    for (int s = 0; s < NST - 1; s++) {
        if (s < NK) load_stage(s);
        asm volatile("cp.async.commit_group;" ::: "memory");
    }

    int a_row = lane & 15;
    int a_kh  = (lane >> 4) << 3;
    int b_g   = lane >> 3;
    int b_nr  = ((b_g >> 1) << 3) + (lane & 7);
    int b_kh  = (b_g & 1) << 3;

    for (int c = 0; c < NK; c++) {
        asm volatile("cp.async.wait_group %0;" :: "n"(NST - 2) : "memory");
        __syncthreads();

        // refill stage c+NST-1 (that buffer was last read in chunk c-1; safe after sync)
        if (c + NST - 1 < NK) load_stage(c + NST - 1);
        asm volatile("cp.async.commit_group;" ::: "memory");

        uint32_t aB = sb + (c % NST) * STAGE;
#pragma unroll
        for (int kk = 0; kk < 32; kk += 16) {
            uint32_t bh[8], bl[8], ah[16], al[16];
#pragma unroll
            for (int f2 = 0; f2 < 2; f2++) {
                uint32_t off = (uint32_t)((wn * 32 + f2 * 16 + b_nr) * LDSW + (kk + b_kh) * 2);
                ldm_x4(aB + TILEB + off, &bh[f2 * 4]);
                ldm_x4(aB + 2 * TILEB + off, &bl[f2 * 4]);
            }
#pragma unroll
            for (int fm = 0; fm < 4; fm++) {
                uint32_t off = (uint32_t)((wm * 64 + fm * 16 + a_row) * LDSW + (kk + a_kh) * 2);
                ldm_x4(aB + off, &ah[fm * 4]);
                if (NTERMS == 3) ldm_x4(aB + 3 * TILEB + off, &al[fm * 4]);
            }
#pragma unroll
            for (int fm = 0; fm < 4; fm++)
#pragma unroll
                for (int fn = 0; fn < 4; fn++) {
                    mma16816(acc[fm][fn], &ah[fm * 4], &bh[fn * 2]);
                    mma16816(acc[fm][fn], &ah[fm * 4], &bl[fn * 2]);
                    if (NTERMS == 3) mma16816(acc[fm][fn], &al[fm * 4], &bh[fn * 2]);
                }
        }
    }

    // epilogue: direct stores + bias
    int mbase = m0 + wm * 64 + (lane >> 2);
    int nbase = n0 + wn * 32 + ((lane & 3) << 1);
#pragma unroll
    for (int fm = 0; fm < 4; fm++) {
#pragma unroll
        for (int fn = 0; fn < 4; fn++) {
            int m = mbase + fm * 16;
            int n = nbase + fn * 8;
            float* d = acc[fm][fn];
            if (n < Nvalid) {
                float bv = bias[n];
                C[(long)m * Nvalid + n]       = d[0] + bv;
                C[(long)(m + 8) * Nvalid + n] = d[2] + bv;
            }
            if (n + 1 < Nvalid) {
                float bv = bias[n + 1];
                C[(long)m * Nvalid + n + 1]       = d[1] + bv;
                C[(long)(m + 8) * Nvalid + n + 1] = d[3] + bv;
            }
        }
    }
}

// ================= persistent LSTM recurrence =================
__global__ __launch_bounds__(192) void lstm_persist(
    const float* __restrict__ dh, const float* __restrict__ dctx,
    const float* __restrict__ Whh, const float* __restrict__ bhh,
    float* __restrict__ allh, float* __restrict__ selctx,
    __nv_bfloat16* __restrict__ ahi)
{
    __shared__ __align__(16) float hs[B_ * H_];
    int tid = threadIdx.x, wid = tid >> 5, lane = tid & 31;
    int u = blockIdx.x * LSTM_WARPS + wid;

    const float4* wp0 = (const float4*)(Whh + (long)(0 * H_ + u) * H_);
    const float4* wp1 = (const float4*)(Whh + (long)(1 * H_ + u) * H_);
    const float4* wp2 = (const float4*)(Whh + (long)(2 * H_ + u) * H_);
    const float4* wp3 = (const float4*)(Whh + (long)(3 * H_ + u) * H_);
    const float4* h4 = (const float4*)hs;

    float creg = 0.0f, b0r = 0.0f, b1r = 0.0f, b2r = 0.0f, b3r = 0.0f;
    float x0 = 0.f, x1 = 0.f, x2 = 0.f, x3 = 0.f;
    int lastb = 0;
    if (lane < 16) {
        creg = dctx[lane * H_ + u];
        lastb = g_last[lane];
        b0r = bhh[0 * H_ + u]; b1r = bhh[1 * H_ + u];
        b2r = bhh[2 * H_ + u]; b3r = bhh[3 * H_ + u];
        const float* xr = g_xg + ((long)lane * T_ + 0) * G_;
        x0 = xr[0 * H_ + u]; x1 = xr[1 * H_ + u];
        x2 = xr[2 * H_ + u]; x3 = xr[3 * H_ + u];
    }

    for (int t = 0; t < T_; t++) {
        float nx0 = 0.f, nx1 = 0.f, nx2 = 0.f, nx3 = 0.f;
        if (lane < 16 && t + 1 < T_) {
            const float* xr = g_xg + ((long)lane * T_ + t + 1) * G_;
            nx0 = __ldcg(xr + 0 * H_ + u); nx1 = __ldcg(xr + 1 * H_ + u);
            nx2 = __ldcg(xr + 2 * H_ + u); nx3 = __ldcg(xr + 3 * H_ + u);
        }

        if (t == 0) {
            for (int i4 = tid; i4 < B_ * H_ / 4; i4 += 192)
                ((float4*)hs)[i4] = __ldcg((const float4*)dh + i4);
        } else {
            for (int i4 = tid; i4 < B_ * H_ / 4; i4 += 192) {
                int b = i4 / (H_ / 4), q = i4 - b * (H_ / 4);
                ((float4*)hs)[i4] = __ldcg((const float4*)(allh + ((long)b * T_ + t - 1) * H_) + q);
            }
        }
        __syncthreads();

        float acc[4][16];
#pragma unroll
        for (int g = 0; g < 4; g++)
#pragma unroll
            for (int b = 0; b < 16; b++) acc[g][b] = 0.0f;

#pragma unroll
        for (int ch = 0; ch < 6; ch++) {
            int k4 = ch * 32 + lane;
            float4 w0 = wp0[k4], w1 = wp1[k4], w2 = wp2[k4], w3 = wp3[k4];
#pragma unroll
            for (int b = 0; b < 16; b++) {
                float4 h = h4[b * 192 + k4];
                acc[0][b] = fmaf(w0.x, h.x, fmaf(w0.y, h.y, fmaf(w0.z, h.z, fmaf(w0.w, h.w, acc[0][b]))));
                acc[1][b] = fmaf(w1.x, h.x, fmaf(w1.y, h.y, fmaf(w1.z, h.z, fmaf(w1.w, h.w, acc[1][b]))));
                acc[2][b] = fmaf(w2.x, h.x, fmaf(w2.y, h.y, fmaf(w2.z, h.z, fmaf(w2.w, h.w, acc[2][b]))));
                acc[3][b] = fmaf(w3.x, h.x, fmaf(w3.y, h.y, fmaf(w3.z, h.z, fmaf(w3.w, h.w, acc[3][b]))));
            }
        }
#pragma unroll
        for (int g = 0; g < 4; g++)
#pragma unroll
            for (int b = 0; b < 16; b++) {
                float v = acc[g][b];
#pragma unroll
                for (int off = 16; off; off >>= 1) v += __shfl_xor_sync(0xffffffffu, v, off);
                acc[g][b] = v;
            }

        if (lane < 16) {
            int b = lane;
            long m = (long)b * T_ + t;
            float xi = acc[0][b] + x0 + b0r;
            float xf = acc[1][b] + x1 + b1r;
            float xg = acc[2][b] + x2 + b2r;
            float xo = acc[3][b] + x3 + b3r;
            float si = 1.0f / (1.0f + expf(-xi));
            float sf = 1.0f / (1.0f + expf(-xf));
            float so = 1.0f / (1.0f + expf(-xo));
            float tg = tanhf(xg);
            creg = sf * creg + si * tg;
            float h = so * tanhf(creg);
            allh[m * H_ + u] = h;
            ahi[m * H_ + u] = __float2bfloat16(h);
            if (t == lastb) selctx[b * H_ + u] = creg;
        }
        x0 = nx0; x1 = nx1; x2 = nx2; x3 = nx3;

        if (t + 1 < T_) {
            __syncthreads();              // orders all threads' h-stores before tid0's release
            if (tid == 0) {
                red_release_add(&g_bar, 1u);   // cumulative release publishes block's writes
                unsigned tgt = (unsigned)(LSTM_BLOCKS * (t + 1));
                while (ld_acq(&g_bar) < tgt) { }
            }
            __syncthreads();
        }
    }
}

// ================= fused log-softmax =================
__global__ void softmax_k(float* __restrict__ lp) {
    __shared__ float red[256];
    int m = blockIdx.x;
    int tid = threadIdx.x;
    float* row = lp + (long)m * V_;
    float mx = -1e30f;
    for (int j = tid; j < V_; j += 256) mx = fmaxf(mx, row[j]);
    red[tid] = mx; __syncthreads();
    for (int s = 128; s; s >>= 1) { if (tid < s) red[tid] = fmaxf(red[tid], red[tid + s]); __syncthreads(); }
    mx = red[0];
    __syncthreads();
    float sum = 0.0f;
    for (int j = tid; j < V_; j += 256) sum += fexp(row[j] - mx);
    red[tid] = sum; __syncthreads();
    for (int s = 128; s; s >>= 1) { if (tid < s) red[tid] += red[tid + s]; __syncthreads(); }
    float l = mx + logf(red[0]);
    __syncthreads();
    for (int j = tid; j < V_; j += 256) row[j] -= l;
}

// ================= launch =================
extern "C" void kernel_launch(void* const* d_in, const int* in_sizes, int n_in,
                              void* d_out, int out_size)
{
    const int*   ids  = (const int*)d_in[0];
    const int*   mask = (const int*)d_in[1];
    const float* dh   = (const float*)d_in[2];
    const float* dc   = (const float*)d_in[3];
    const float* dapp = (const float*)d_in[4];
    const float* emb  = (const float*)d_in[5];
    const float* Wih  = (const float*)d_in[6];
    const float* Whh  = (const float*)d_in[7];
    const float* bih  = (const float*)d_in[8];
    const float* bhh  = (const float*)d_in[9];
    const float* lmw  = (const float*)d_in[10];
    const float* lmb  = (const float*)d_in[11];
    (void)in_sizes; (void)n_in; (void)out_size;

    float* out    = (float*)d_out;
    float* allh   = out;
    float* selctx = out + (long)MROWS * H_;
    float* lp     = selctx + B_ * H_;

    constexpr int SMEM3 = 4 * 4 * TILEB;   // <3,4>: 163840, 1 CTA/SM
    constexpr int SMEM2 = 3 * 3 * TILEB;   // <2,3>:  92160, 2 CTAs/SM

    static int attr_set = 0;
    if (!attr_set) {
        cudaFuncSetAttribute((const void*)hmma_gemm<3,4>, cudaFuncAttributeMaxDynamicSharedMemorySize, SMEM3);
        cudaFuncSetAttribute((const void*)hmma_gemm<2,3>, cudaFuncAttributeMaxDynamicSharedMemorySize, SMEM2);
        attr_set = 1;
    }

    __nv_bfloat16 *whi, *wlo, *ahi, *xah, *xal, *wihh, *wihl;
    float* xg;
    cudaGetSymbolAddress((void**)&whi, g_whi);
    cudaGetSymbolAddress((void**)&wlo, g_wlo);
    cudaGetSymbolAddress((void**)&ahi, g_ahi);
    cudaGetSymbolAddress((void**)&xah, g_xah);
    cudaGetSymbolAddress((void**)&xal, g_xal);
    cudaGetSymbolAddress((void**)&wihh, g_wihh);
    cudaGetSymbolAddress((void**)&wihl, g_wihl);
    cudaGetSymbolAddress((void**)&xg, g_xg);

    setup_k<<<1, 32>>>(mask);

    conv_gather<<<1024, 256>>>(ids, emb, dapp, xah, xal);
    conv_k<<<1024, 256>>>(Wih, wihh, wihl, (long)G_ * KX / 4);

    // xg = [emb||app] @ W_ih^T + b_ih  (3-term: feeds recurrence, keep accuracy)
    hmma_gemm<3,4><<<dim3(MROWS / 128, G_ / 128), 256, SMEM3>>>(
        xah, xal, wihh, wihl, bih, xg, KX, G_);

    conv_k<<<4096, 256>>>(lmw, whi, wlo, (long)V_ * H_ / 4);

    lstm_persist<<<LSTM_BLOCKS, 192>>>(dh, dc, Whh, bhh, allh, selctx, ahi);

    // logits = hiddens(bf16 hi) @ lm_w(hi+lo)^T + lm_b  (2-term; 2 CTAs/SM)
    hmma_gemm<2,3><<<dim3(MROWS / 128, (V_ + 127) / 128), 256, SMEM2>>>(
        ahi, ahi, whi, wlo, lmb, lp, H_, V_);

    softmax_k<<<MROWS, 256>>>(lp);
}

// round 15
// speedup vs baseline: 2.7341x; 1.1206x over previous
#include <cuda_runtime.h>
#include <cuda_bf16.h>
#include <cstdint>

#define V_  50257
#define H_  768
#define B_  16
#define T_  128
#define G_  3072          // 4*H
#define KX  1536          // 2*H
#define MROWS 2048        // B*T

#define LSTM_BLOCKS 128
#define LSTM_WARPS  6     // units per block; 128*6 = 768 = H_

// ================= scratch (no cudaMalloc allowed) =================
__device__ float g_xg[(long)MROWS * G_];                 // input-side gate projections
__device__ int   g_last[B_];
__device__ unsigned g_bar;                               // grid barrier counter
__device__ __nv_bfloat16 g_whi[(long)V_ * H_];           // lm_w hi (bf16)
__device__ __nv_bfloat16 g_ahi[(long)MROWS * H_];        // hiddens hi (bf16)
__device__ __nv_bfloat16 g_xah[(long)MROWS * KX];        // [emb||app] hi
__device__ __nv_bfloat16 g_xal[(long)MROWS * KX];        // [emb||app] lo
__device__ __nv_bfloat16 g_wihh[(long)G_ * KX];          // W_ih hi
__device__ __nv_bfloat16 g_wihl[(long)G_ * KX];          // W_ih lo

// ================= small ptx helpers (baseline PTX only) =================
__device__ __forceinline__ uint32_t smem_to_u32(const void* p) {
    uint32_t a;
    asm("{ .reg .u64 t; cvta.to.shared.u64 t, %1; cvt.u32.u64 %0, t; }" : "=r"(a) : "l"(p));
    return a;
}
__device__ __forceinline__ void cpasync16(uint32_t dst, const void* src, uint32_t sz) {
    asm volatile("cp.async.cg.shared.global [%0], [%1], 16, %2;\n"
        :: "r"(dst), "l"(src), "r"(sz) : "memory");
}
__device__ __forceinline__ void ldm_x4(uint32_t addr, uint32_t* r) {
    asm volatile("ldmatrix.sync.aligned.m8n8.x4.shared.b16 {%0,%1,%2,%3}, [%4];"
        : "=r"(r[0]), "=r"(r[1]), "=r"(r[2]), "=r"(r[3]) : "r"(addr));
}
__device__ __forceinline__ void mma16816(float* d, const uint32_t* a, const uint32_t* b) {
    asm volatile("mma.sync.aligned.m16n8k16.row.col.f32.bf16.bf16.f32 "
        "{%0,%1,%2,%3}, {%4,%5,%6,%7}, {%8,%9}, {%0,%1,%2,%3};"
        : "+f"(d[0]), "+f"(d[1]), "+f"(d[2]), "+f"(d[3])
        : "r"(a[0]), "r"(a[1]), "r"(a[2]), "r"(a[3]), "r"(b[0]), "r"(b[1]));
}
__device__ __forceinline__ unsigned ld_acq(const unsigned* p) {
    unsigned v;
    asm volatile("ld.acquire.gpu.global.u32 %0, [%1];" : "=r"(v) : "l"(p) : "memory");
    return v;
}
__device__ __forceinline__ void red_release_add(unsigned* p, unsigned v) {
    asm volatile("red.release.gpu.global.add.u32 [%0], %1;" :: "l"(p), "r"(v) : "memory");
}

// ================= fast exp =================
__device__ __forceinline__ float fexp(float x) {
    x = fmaxf(x, -20.0f);
    float t  = x * 1.4426950408889634f;
    float z  = t + 12582912.0f;
    float nf = z - 12582912.0f;
    float f  = t - nf;
    int   n  = (int)nf;
    float p = fmaf(0.00133335581f, f, 0.00961812911f);
    p = fmaf(p, f, 0.0555041087f);
    p = fmaf(p, f, 0.240226507f);
    p = fmaf(p, f, 0.69314718056f);
    p = fmaf(p, f, 1.0f);
    return p * __int_as_float((n + 127) << 23);
}

// ================= setup =================
__global__ void setup_k(const int* __restrict__ mask) {
    int idx = threadIdx.x;
    if (idx < B_) {
        int s = 0;
        for (int t = 0; t < T_; t++) s += mask[idx * T_ + t];
        g_last[idx] = s - 1;
    }
    if (idx == B_) g_bar = 0u;
}

// ================= hi/lo bf16 conversions =================
__global__ void conv_k(const float* __restrict__ src, __nv_bfloat16* __restrict__ hi,
                       __nv_bfloat16* __restrict__ lo, long n4) {
    long i = (long)blockIdx.x * 256 + threadIdx.x;
    long stride = (long)gridDim.x * 256;
    for (; i < n4; i += stride) {
        float4 v = ((const float4*)src)[i];
        __nv_bfloat16 h0 = __float2bfloat16(v.x), h1 = __float2bfloat16(v.y);
        __nv_bfloat16 h2 = __float2bfloat16(v.z), h3 = __float2bfloat16(v.w);
        __nv_bfloat16 l0 = __float2bfloat16(v.x - __bfloat162float(h0));
        __nv_bfloat16 l1 = __float2bfloat16(v.y - __bfloat162float(h1));
        __nv_bfloat16 l2 = __float2bfloat16(v.z - __bfloat162float(h2));
        __nv_bfloat16 l3 = __float2bfloat16(v.w - __bfloat162float(h3));
        ((__nv_bfloat162*)hi)[i * 2 + 0] = __nv_bfloat162(h0, h1);
        ((__nv_bfloat162*)hi)[i * 2 + 1] = __nv_bfloat162(h2, h3);
        ((__nv_bfloat162*)lo)[i * 2 + 0] = __nv_bfloat162(l0, l1);
        ((__nv_bfloat162*)lo)[i * 2 + 1] = __nv_bfloat162(l2, l3);
    }
}

// hi-only conversion (for lm_w: 1-term logits GEMM needs no residual)
__global__ void conv_hi(const float* __restrict__ src, __nv_bfloat16* __restrict__ hi, long n4) {
    long i = (long)blockIdx.x * 256 + threadIdx.x;
    long stride = (long)gridDim.x * 256;
    for (; i < n4; i += stride) {
        float4 v = ((const float4*)src)[i];
        ((__nv_bfloat162*)hi)[i * 2 + 0] =
            __nv_bfloat162(__float2bfloat16(v.x), __float2bfloat16(v.y));
        ((__nv_bfloat162*)hi)[i * 2 + 1] =
            __nv_bfloat162(__float2bfloat16(v.z), __float2bfloat16(v.w));
    }
}

// build [emb(ids) || append] as hi/lo bf16, rows = MROWS, K = KX
__global__ void conv_gather(const int* __restrict__ ids, const float* __restrict__ emb,
                            const float* __restrict__ app,
                            __nv_bfloat16* __restrict__ hi, __nv_bfloat16* __restrict__ lo) {
    long total = (long)MROWS * (KX / 4);
    long i = (long)blockIdx.x * 256 + threadIdx.x;
    long stride = (long)gridDim.x * 256;
    for (; i < total; i += stride) {
        int m = (int)(i / (KX / 4));
        int q = (int)(i - (long)m * (KX / 4));
        int k = q * 4;
        const float* p;
        if (k < H_) p = emb + (long)ids[m] * H_ + k;
        else        p = app + (long)(m >> 7) * H_ + (k - H_);
        float4 v = *(const float4*)p;
        __nv_bfloat16 h0 = __float2bfloat16(v.x), h1 = __float2bfloat16(v.y);
        __nv_bfloat16 h2 = __float2bfloat16(v.z), h3 = __float2bfloat16(v.w);
        __nv_bfloat16 l0 = __float2bfloat16(v.x - __bfloat162float(h0));
        __nv_bfloat16 l1 = __float2bfloat16(v.y - __bfloat162float(h1));
        __nv_bfloat16 l2 = __float2bfloat16(v.z - __bfloat162float(h2));
        __nv_bfloat16 l3 = __float2bfloat16(v.w - __bfloat162float(h3));
        long o = (long)m * (KX / 2) + q * 2;
        ((__nv_bfloat162*)hi)[o + 0] = __nv_bfloat162(h0, h1);
        ((__nv_bfloat162*)hi)[o + 1] = __nv_bfloat162(h2, h3);
        ((__nv_bfloat162*)lo)[o + 0] = __nv_bfloat162(l0, l1);
        ((__nv_bfloat162*)lo)[o + 1] = __nv_bfloat162(l2, l3);
    }
}

// ================= HMMA GEMM (templated terms/stages): C = A @ B^T + bias =================
// Block 128x128, warp tile 64x32 (8 warps 2m x 4n), BK=32, NST-stage cp.async pipeline,
// ONE __syncthreads per K-chunk.
// NTERMS=3: AhBh+AhBl+AlBh (1 CTA/SM). NTERMS=1: AhBh only (2 CTAs/SM, small smem).
#define LDSW  80                     // padded row stride bytes (64B data + 16B pad)
#define TILEB (128 * LDSW)           // 10240 B per 128-row tile

template<int NTERMS, int NST>
__global__ __launch_bounds__(256, (NTERMS == 1 ? 2 : 1)) void hmma_gemm(
    const __nv_bfloat16* __restrict__ Ah, const __nv_bfloat16* __restrict__ Al,
    const __nv_bfloat16* __restrict__ Bh, const __nv_bfloat16* __restrict__ Bl,
    const float* __restrict__ bias, float* __restrict__ C,
    int K, int Nvalid)
{
    constexpr int NMAT  = (NTERMS == 3) ? 4 : (NTERMS == 2 ? 3 : 2);
    constexpr int STAGE = NMAT * TILEB;
    // stage layout: Ah @0, Bh @TILEB, [Bl @2*TILEB], [Al @3*TILEB]

    extern __shared__ __align__(128) char smem[];
    uint32_t sb = smem_to_u32(smem);
    int tid = threadIdx.x;
    int lane = tid & 31, wid = tid >> 5;
    int wm = wid & 1, wn = wid >> 1;
    int m0 = blockIdx.x * 128;          // m-fast for B-tile L2 reuse
    int n0 = blockIdx.y * 128;
    int NK = K >> 5;

    float acc[4][4][4];
#pragma unroll
    for (int a = 0; a < 4; a++)
#pragma unroll
        for (int b = 0; b < 4; b++)
#pragma unroll
            for (int c = 0; c < 4; c++) acc[a][b][c] = 0.0f;

    int lrow = tid >> 2;     // 0..63
    int lq   = tid & 3;

    auto load_stage = [&](int stg) {
        int k0 = stg << 5;
        uint32_t db = sb + (stg % NST) * STAGE;
#pragma unroll
        for (int half = 0; half < 2; half++) {
            int r = half * 64 + lrow;
            uint32_t dof = (uint32_t)(r * LDSW + lq * 16);
            long asrc = (long)(m0 + r) * K + k0 + lq * 8;
            cpasync16(db + dof, Ah + asrc, 16);
            if (NTERMS == 3) cpasync16(db + 3 * TILEB + dof, Al + asrc, 16);
            int n = n0 + r;
            uint32_t sz = 16;
            if (n >= Nvalid) { n = 0; sz = 0; }
            long bsrc = (long)n * K + k0 + lq * 8;
            cpasync16(db + TILEB + dof, Bh + bsrc, sz);
            if (NTERMS >= 2) cpasync16(db + 2 * TILEB + dof, Bl + bsrc, sz);
        }
    };

    // prologue: fill NST-1 stages
#pragma unroll
    for (int s = 0; s < NST - 1; s++) {
        if (s < NK) load_stage(s);
        asm volatile("cp.async.commit_group;" ::: "memory");
    }

    int a_row = lane & 15;
    int a_kh  = (lane >> 4) << 3;
    int b_g   = lane >> 3;
    int b_nr  = ((b_g >> 1) << 3) + (lane & 7);
    int b_kh  = (b_g & 1) << 3;

    for (int c = 0; c < NK; c++) {
        asm volatile("cp.async.wait_group %0;" :: "n"(NST - 2) : "memory");
        __syncthreads();

        // refill stage c+NST-1 (that buffer was last read in chunk c-1; safe after sync)
        if (c + NST - 1 < NK) load_stage(c + NST - 1);
        asm volatile("cp.async.commit_group;" ::: "memory");

        uint32_t aB = sb + (c % NST) * STAGE;
#pragma unroll
        for (int kk = 0; kk < 32; kk += 16) {
            uint32_t bh[8], bl[8], ah[16], al[16];
#pragma unroll
            for (int f2 = 0; f2 < 2; f2++) {
                uint32_t off = (uint32_t)((wn * 32 + f2 * 16 + b_nr) * LDSW + (kk + b_kh) * 2);
                ldm_x4(aB + TILEB + off, &bh[f2 * 4]);
                if (NTERMS >= 2) ldm_x4(aB + 2 * TILEB + off, &bl[f2 * 4]);
            }
#pragma unroll
            for (int fm = 0; fm < 4; fm++) {
                uint32_t off = (uint32_t)((wm * 64 + fm * 16 + a_row) * LDSW + (kk + a_kh) * 2);
                ldm_x4(aB + off, &ah[fm * 4]);
                if (NTERMS == 3) ldm_x4(aB + 3 * TILEB + off, &al[fm * 4]);
            }
#pragma unroll
            for (int fm = 0; fm < 4; fm++)
#pragma unroll
                for (int fn = 0; fn < 4; fn++) {
                    mma16816(acc[fm][fn], &ah[fm * 4], &bh[fn * 2]);
                    if (NTERMS >= 2) mma16816(acc[fm][fn], &ah[fm * 4], &bl[fn * 2]);
                    if (NTERMS == 3) mma16816(acc[fm][fn], &al[fm * 4], &bh[fn * 2]);
                }
        }
    }

    // epilogue: direct stores + bias
    int mbase = m0 + wm * 64 + (lane >> 2);
    int nbase = n0 + wn * 32 + ((lane & 3) << 1);
#pragma unroll
    for (int fm = 0; fm < 4; fm++) {
#pragma unroll
        for (int fn = 0; fn < 4; fn++) {
            int m = mbase + fm * 16;
            int n = nbase + fn * 8;
            float* d = acc[fm][fn];
            if (n < Nvalid) {
                float bv = bias[n];
                C[(long)m * Nvalid + n]       = d[0] + bv;
                C[(long)(m + 8) * Nvalid + n] = d[2] + bv;
            }
            if (n + 1 < Nvalid) {
                float bv = bias[n + 1];
                C[(long)m * Nvalid + n + 1]       = d[1] + bv;
                C[(long)(m + 8) * Nvalid + n + 1] = d[3] + bv;
            }
        }
    }
}

// ================= persistent LSTM recurrence =================
__global__ __launch_bounds__(192) void lstm_persist(
    const float* __restrict__ dh, const float* __restrict__ dctx,
    const float* __restrict__ Whh, const float* __restrict__ bhh,
    float* __restrict__ allh, float* __restrict__ selctx,
    __nv_bfloat16* __restrict__ ahi)
{
    __shared__ __align__(16) float hs[B_ * H_];
    int tid = threadIdx.x, wid = tid >> 5, lane = tid & 31;
    int u = blockIdx.x * LSTM_WARPS + wid;

    const float4* wp0 = (const float4*)(Whh + (long)(0 * H_ + u) * H_);
    const float4* wp1 = (const float4*)(Whh + (long)(1 * H_ + u) * H_);
    const float4* wp2 = (const float4*)(Whh + (long)(2 * H_ + u) * H_);
    const float4* wp3 = (const float4*)(Whh + (long)(3 * H_ + u) * H_);
    const float4* h4 = (const float4*)hs;

    float creg = 0.0f, b0r = 0.0f, b1r = 0.0f, b2r = 0.0f, b3r = 0.0f;
    float x0 = 0.f, x1 = 0.f, x2 = 0.f, x3 = 0.f;
    int lastb = 0;
    if (lane < 16) {
        creg = dctx[lane * H_ + u];
        lastb = g_last[lane];
        b0r = bhh[0 * H_ + u]; b1r = bhh[1 * H_ + u];
        b2r = bhh[2 * H_ + u]; b3r = bhh[3 * H_ + u];
        const float* xr = g_xg + ((long)lane * T_ + 0) * G_;
        x0 = xr[0 * H_ + u]; x1 = xr[1 * H_ + u];
        x2 = xr[2 * H_ + u]; x3 = xr[3 * H_ + u];
    }

    for (int t = 0; t < T_; t++) {
        float nx0 = 0.f, nx1 = 0.f, nx2 = 0.f, nx3 = 0.f;
        if (lane < 16 && t + 1 < T_) {
            const float* xr = g_xg + ((long)lane * T_ + t + 1) * G_;
            nx0 = __ldcg(xr + 0 * H_ + u); nx1 = __ldcg(xr + 1 * H_ + u);
            nx2 = __ldcg(xr + 2 * H_ + u); nx3 = __ldcg(xr + 3 * H_ + u);
        }

        if (t == 0) {
            for (int i4 = tid; i4 < B_ * H_ / 4; i4 += 192)
                ((float4*)hs)[i4] = __ldcg((const float4*)dh + i4);
        } else {
            for (int i4 = tid; i4 < B_ * H_ / 4; i4 += 192) {
                int b = i4 / (H_ / 4), q = i4 - b * (H_ / 4);
                ((float4*)hs)[i4] = __ldcg((const float4*)(allh + ((long)b * T_ + t - 1) * H_) + q);
            }
        }
        __syncthreads();

        float acc[4][16];
#pragma unroll
        for (int g = 0; g < 4; g++)
#pragma unroll
            for (int b = 0; b < 16; b++) acc[g][b] = 0.0f;

#pragma unroll
        for (int ch = 0; ch < 6; ch++) {
            int k4 = ch * 32 + lane;
            float4 w0 = wp0[k4], w1 = wp1[k4], w2 = wp2[k4], w3 = wp3[k4];
#pragma unroll
            for (int b = 0; b < 16; b++) {
                float4 h = h4[b * 192 + k4];
                acc[0][b] = fmaf(w0.x, h.x, fmaf(w0.y, h.y, fmaf(w0.z, h.z, fmaf(w0.w, h.w, acc[0][b]))));
                acc[1][b] = fmaf(w1.x, h.x, fmaf(w1.y, h.y, fmaf(w1.z, h.z, fmaf(w1.w, h.w, acc[1][b]))));
                acc[2][b] = fmaf(w2.x, h.x, fmaf(w2.y, h.y, fmaf(w2.z, h.z, fmaf(w2.w, h.w, acc[2][b]))));
                acc[3][b] = fmaf(w3.x, h.x, fmaf(w3.y, h.y, fmaf(w3.z, h.z, fmaf(w3.w, h.w, acc[3][b]))));
            }
        }
#pragma unroll
        for (int g = 0; g < 4; g++)
#pragma unroll
            for (int b = 0; b < 16; b++) {
                float v = acc[g][b];
#pragma unroll
                for (int off = 16; off; off >>= 1) v += __shfl_xor_sync(0xffffffffu, v, off);
                acc[g][b] = v;
            }

        if (lane < 16) {
            int b = lane;
            long m = (long)b * T_ + t;
            float xi = acc[0][b] + x0 + b0r;
            float xf = acc[1][b] + x1 + b1r;
            float xg = acc[2][b] + x2 + b2r;
            float xo = acc[3][b] + x3 + b3r;
            float si = 1.0f / (1.0f + expf(-xi));
            float sf = 1.0f / (1.0f + expf(-xf));
            float so = 1.0f / (1.0f + expf(-xo));
            float tg = tanhf(xg);
            creg = sf * creg + si * tg;
            float h = so * tanhf(creg);
            allh[m * H_ + u] = h;
            ahi[m * H_ + u] = __float2bfloat16(h);
            if (t == lastb) selctx[b * H_ + u] = creg;
        }
        x0 = nx0; x1 = nx1; x2 = nx2; x3 = nx3;

        if (t + 1 < T_) {
            __syncthreads();              // orders all threads' h-stores before tid0's release
            if (tid == 0) {
                red_release_add(&g_bar, 1u);   // cumulative release publishes block's writes
                unsigned tgt = (unsigned)(LSTM_BLOCKS * (t + 1));
                while (ld_acq(&g_bar) < tgt) { }
            }
            __syncthreads();
        }
    }
}

// ================= fused log-softmax (online max+sum: 2 reads + 1 write) =================
__global__ void softmax_k(float* __restrict__ lp) {
    __shared__ float rm[256], rs[256];
    int m = blockIdx.x;
    int tid = threadIdx.x;
    float* row = lp + (long)m * V_;

    float mx = -1e30f, s = 0.0f;
    for (int j = tid; j < V_; j += 256) {
        float v = row[j];
        if (v <= mx) {
            s += fexp(v - mx);
        } else {
            s = fmaf(s, fexp(mx - v), 1.0f);
            mx = v;
        }
    }
    rm[tid] = mx; rs[tid] = s;
    __syncthreads();
    for (int str = 128; str; str >>= 1) {
        if (tid < str) {
            float m1 = rm[tid], s1 = rs[tid];
            float m2 = rm[tid + str], s2 = rs[tid + str];
            float mc = fmaxf(m1, m2);
            rm[tid] = mc;
            rs[tid] = s1 * fexp(m1 - mc) + s2 * fexp(m2 - mc);
        }
        __syncthreads();
    }
    float l = rm[0] + logf(rs[0]);
    for (int j = tid; j < V_; j += 256) row[j] -= l;
}

// ================= launch =================
extern "C" void kernel_launch(void* const* d_in, const int* in_sizes, int n_in,
                              void* d_out, int out_size)
{
    const int*   ids  = (const int*)d_in[0];
    const int*   mask = (const int*)d_in[1];
    const float* dh   = (const float*)d_in[2];
    const float* dc   = (const float*)d_in[3];
    const float* dapp = (const float*)d_in[4];
    const float* emb  = (const float*)d_in[5];
    const float* Wih  = (const float*)d_in[6];
    const float* Whh  = (const float*)d_in[7];
    const float* bih  = (const float*)d_in[8];
    const float* bhh  = (const float*)d_in[9];
    const float* lmw  = (const float*)d_in[10];
    const float* lmb  = (const float*)d_in[11];
    (void)in_sizes; (void)n_in; (void)out_size;

    float* out    = (float*)d_out;
    float* allh   = out;
    float* selctx = out + (long)MROWS * H_;
    float* lp     = selctx + B_ * H_;

    constexpr int SMEM3 = 4 * 4 * TILEB;   // <3,4>: 163840, 1 CTA/SM
    constexpr int SMEM1 = 4 * 2 * TILEB;   // <1,4>:  81920, 2 CTAs/SM

    static int attr_set = 0;
    if (!attr_set) {
        cudaFuncSetAttribute((const void*)hmma_gemm<3,4>, cudaFuncAttributeMaxDynamicSharedMemorySize, SMEM3);
        cudaFuncSetAttribute((const void*)hmma_gemm<1,4>, cudaFuncAttributeMaxDynamicSharedMemorySize, SMEM1);
        attr_set = 1;
    }

    __nv_bfloat16 *whi, *ahi, *xah, *xal, *wihh, *wihl;
    float* xg;
    cudaGetSymbolAddress((void**)&whi, g_whi);
    cudaGetSymbolAddress((void**)&ahi, g_ahi);
    cudaGetSymbolAddress((void**)&xah, g_xah);
    cudaGetSymbolAddress((void**)&xal, g_xal);
    cudaGetSymbolAddress((void**)&wihh, g_wihh);
    cudaGetSymbolAddress((void**)&wihl, g_wihl);
    cudaGetSymbolAddress((void**)&xg, g_xg);

    setup_k<<<1, 32>>>(mask);

    conv_gather<<<1024, 256>>>(ids, emb, dapp, xah, xal);
    conv_k<<<1024, 256>>>(Wih, wihh, wihl, (long)G_ * KX / 4);

    // xg = [emb||app] @ W_ih^T + b_ih  (3-term: feeds recurrence, keep accuracy)
    hmma_gemm<3,4><<<dim3(MROWS / 128, G_ / 128), 256, SMEM3>>>(
        xah, xal, wihh, wihl, bih, xg, KX, G_);

    conv_hi<<<4096, 256>>>(lmw, whi, (long)V_ * H_ / 4);

    lstm_persist<<<LSTM_BLOCKS, 192>>>(dh, dc, Whh, bhh, allh, selctx, ahi);

    // logits = hiddens(bf16) @ lm_w(bf16)^T + lm_b  (1-term; 2 CTAs/SM, 80KB smem)
    hmma_gemm<1,4><<<dim3(MROWS / 128, (V_ + 127) / 128), 256, SMEM1>>>(
        ahi, ahi, whi, whi, lmb, lp, H_, V_);

    softmax_k<<<MROWS, 256>>>(lp);
}